// round 1
// baseline (speedup 1.0000x reference)
#include <cuda_runtime.h>
#include <math.h>

// Problem constants
#define Bn 64
#define Un 1024
#define Hn 16
#define Mn 512
#define HSn 64
#define Dn 4
#define NSLOT 513            // M+1
#define NRr 8208             // H*(M+1)
#define NWw 8192             // H*M
#define U4 256               // U/4
#define MCH 64               // slots per pass-block
#define NCH 8                // M / MCH

// -------- scratch (device globals; no runtime allocation) --------
__device__ float g_mem [Bn*Mn*Un];     // working memory (layers 1..2 state)
__device__ float g_part[Bn*NCH*Un];    // per-chunk partial sums
__device__ float g_state[Bn*Un];       // memstate
__device__ float g_rlog[Bn*NRr];
__device__ float g_rw  [Bn*NRr];
__device__ float g_wlog[Bn*NWw];
__device__ float g_ww  [Bn*NWw];
__device__ float g_read[Bn*Un];
__device__ float g_vecA[Bn*Un];
__device__ float g_vecB[Bn*Un];
__device__ float g_kpart[4*Bn*Un];     // K-split partials for Wk GEMM

// -------- kernels --------

// Partial slot-sum of memory: part[b][chunk][u] = sum_{m in chunk} mem[b][m][u]
__global__ __launch_bounds__(256) void k_slotsum(const float* __restrict__ mem,
                                                 float* __restrict__ part) {
    int b = blockIdx.x, c = blockIdx.y, t = threadIdx.x;
    const float4* m4 = (const float4*)mem + (size_t)(b*Mn + c*MCH)*U4 + t;
    float ax=0.f, ay=0.f, az=0.f, aw=0.f;
    #pragma unroll 4
    for (int i = 0; i < MCH; i++) {
        float4 v = m4[(size_t)i*U4];
        ax += v.x; ay += v.y; az += v.z; aw += v.w;
    }
    ((float4*)part)[(b*NCH + c)*U4 + t] = make_float4(ax, ay, az, aw);
}

// memstate[b][u] = (sum_chunks part + vec[b][u]) / 513
__global__ __launch_bounds__(256) void k_state_fin(const float* __restrict__ part,
                                                   const float* __restrict__ vec,
                                                   float* __restrict__ state) {
    int b = blockIdx.x, t = threadIdx.x;
    float4 a = ((const float4*)vec)[b*U4 + t];
    #pragma unroll
    for (int c = 0; c < NCH; c++) {
        float4 v = ((const float4*)part)[(b*NCH + c)*U4 + t];
        a.x += v.x; a.y += v.y; a.z += v.z; a.w += v.w;
    }
    const float inv = 1.f / 513.f;
    a.x *= inv; a.y *= inv; a.z *= inv; a.w *= inv;
    ((float4*)state)[b*U4 + t] = a;
}

// C[64 x N] (+K-split) = A[64x1024] @ W[1024 x N]
// grid.x = ceil(N/64), grid.z = ksplits (Ksub = 1024/ksplits)
__global__ __launch_bounds__(256) void k_gemm(const float* __restrict__ A,
                                              const float* __restrict__ W,
                                              float* __restrict__ C,
                                              int N, int Ksub) {
    __shared__ float As[32][68];   // [k][i], padded (bank spread on transpose store)
    __shared__ float Ws[32][64];   // [k][j]
    int t  = threadIdx.x;
    int j0 = blockIdx.x * 64;
    int kb = blockIdx.z * Ksub;
    int rg = t >> 4, cg = t & 15;
    float acc[4][4];
    #pragma unroll
    for (int r = 0; r < 4; r++)
        #pragma unroll
        for (int c = 0; c < 4; c++) acc[r][c] = 0.f;

    for (int k0 = kb; k0 < kb + Ksub; k0 += 32) {
        #pragma unroll
        for (int r = 0; r < 8; r++) {              // A tile 64x32
            int idx = t + 256*r;
            int i = idx >> 5, k = idx & 31;
            As[k][i] = A[i*1024 + k0 + k];
        }
        #pragma unroll
        for (int r = 0; r < 8; r++) {              // W tile 32x64
            int idx = t + 256*r;
            int k = idx >> 6, j = idx & 63;
            int gj = j0 + j;
            Ws[k][j] = (gj < N) ? W[(size_t)(k0 + k)*N + gj] : 0.f;
        }
        __syncthreads();
        #pragma unroll
        for (int k = 0; k < 32; k++) {
            float4 a = *(const float4*)&As[k][rg*4];
            float4 w = *(const float4*)&Ws[k][cg*4];
            acc[0][0] += a.x*w.x; acc[0][1] += a.x*w.y; acc[0][2] += a.x*w.z; acc[0][3] += a.x*w.w;
            acc[1][0] += a.y*w.x; acc[1][1] += a.y*w.y; acc[1][2] += a.y*w.z; acc[1][3] += a.y*w.w;
            acc[2][0] += a.z*w.x; acc[2][1] += a.z*w.y; acc[2][2] += a.z*w.z; acc[2][3] += a.z*w.w;
            acc[3][0] += a.w*w.x; acc[3][1] += a.w*w.y; acc[3][2] += a.w*w.z; acc[3][3] += a.w*w.w;
        }
        __syncthreads();
    }
    size_t zo = (size_t)blockIdx.z * 64 * N;
    #pragma unroll
    for (int r = 0; r < 4; r++) {
        int i = rg*4 + r;
        #pragma unroll
        for (int c = 0; c < 4; c++) {
            int j = j0 + cg*4 + c;
            if (j < N) C[zo + (size_t)i*N + j] = acc[r][c];
        }
    }
}

// per-(b,h) softmax over NS slots, logits at stride H, bias added on read.
template <int NS, int NCOLS>
__global__ __launch_bounds__(256) void k_softmax(const float* __restrict__ logit,
                                                 const float* __restrict__ bias,
                                                 float* __restrict__ prob) {
    constexpr int IT = (NS + 31) / 32;
    int gw   = (blockIdx.x * blockDim.x + threadIdx.x) >> 5;
    int lane = threadIdx.x & 31;
    int b = gw >> 4, h = gw & 15;
    const float* base = logit + (size_t)b*NCOLS + h;
    float vals[IT];
    float mx = -1e30f;
    #pragma unroll
    for (int i = 0; i < IT; i++) {
        int s = i*32 + lane;
        float v = -1e30f;
        if (s < NS) v = base[s*Hn] + bias[s*Hn + h];
        vals[i] = v;
        mx = fmaxf(mx, v);
    }
    #pragma unroll
    for (int o = 16; o; o >>= 1) mx = fmaxf(mx, __shfl_xor_sync(0xffffffffu, mx, o));
    float sum = 0.f;
    #pragma unroll
    for (int i = 0; i < IT; i++) {
        int s = i*32 + lane;
        float e = (s < NS) ? __expf(vals[i] - mx) : 0.f;
        vals[i] = e;
        sum += e;
    }
    #pragma unroll
    for (int o = 16; o; o >>= 1) sum += __shfl_xor_sync(0xffffffffu, sum, o);
    float inv = 1.f / sum;
    float* dst = prob + (size_t)b*NCOLS + h;
    #pragma unroll
    for (int i = 0; i < IT; i++) {
        int s = i*32 + lane;
        if (s < NS) dst[s*Hn] = vals[i] * inv;
    }
}

// Weighted read partial: part[b][chunk][u] = sum_{m in chunk} rw[b][m][h(u)] * mem[b][m][u]
__global__ __launch_bounds__(256) void k_wread(const float* __restrict__ mem,
                                               const float* __restrict__ rw,
                                               float* __restrict__ part) {
    __shared__ float rws[MCH*Hn];
    int b = blockIdx.x, c = blockIdx.y, t = threadIdx.x;
    ((float4*)rws)[t] = ((const float4*)(rw + (size_t)b*NRr + c*MCH*Hn))[t];
    __syncthreads();
    int h = t >> 4;
    const float4* m4 = (const float4*)mem + (size_t)(b*Mn + c*MCH)*U4 + t;
    float ax=0.f, ay=0.f, az=0.f, aw=0.f;
    #pragma unroll 4
    for (int i = 0; i < MCH; i++) {
        float4 v = m4[(size_t)i*U4];
        float w = rws[i*Hn + h];
        ax += w*v.x; ay += w*v.y; az += w*v.z; aw += w*v.w;
    }
    ((float4*)part)[(b*NCH + c)*U4 + t] = make_float4(ax, ay, az, aw);
}

// read[b][u] = sum partials + out[b][u] * rw[b][slot=M][h(u)]
__global__ __launch_bounds__(256) void k_read_fin(const float* __restrict__ part,
                                                  const float* __restrict__ outv,
                                                  const float* __restrict__ rw,
                                                  float* __restrict__ readv) {
    int b = blockIdx.x, t = threadIdx.x;
    int h = t >> 4;
    float wl = rw[(size_t)b*NRr + Mn*Hn + h];
    float4 a = ((const float4*)outv)[b*U4 + t];
    a.x *= wl; a.y *= wl; a.z *= wl; a.w *= wl;
    #pragma unroll
    for (int c = 0; c < NCH; c++) {
        float4 v = ((const float4*)part)[(b*NCH + c)*U4 + t];
        a.x += v.x; a.y += v.y; a.z += v.z; a.w += v.w;
    }
    ((float4*)readv)[b*U4 + t] = a;
}

// newval = relu(sum_z kpart[z] + bk)
__global__ __launch_bounds__(256) void k_wk_reduce(const float* __restrict__ part,
                                                   const float* __restrict__ bk,
                                                   float* __restrict__ nv) {
    int b = blockIdx.x, t = threadIdx.x;
    float4 a = ((const float4*)bk)[t];
    #pragma unroll
    for (int z = 0; z < 4; z++) {
        float4 v = ((const float4*)part)[((size_t)z*Bn + b)*U4 + t];
        a.x += v.x; a.y += v.y; a.z += v.z; a.w += v.w;
    }
    a.x = fmaxf(a.x, 0.f); a.y = fmaxf(a.y, 0.f);
    a.z = fmaxf(a.z, 0.f); a.w = fmaxf(a.w, 0.f);
    ((float4*)nv)[b*U4 + t] = a;
}

// mem' = (1-ww)*mem + ww*newval; also emit per-chunk slot-sum partials of mem'
__global__ __launch_bounds__(256) void k_update(const float* __restrict__ memin,
                                                const float* __restrict__ ww,
                                                const float* __restrict__ nv,
                                                float* __restrict__ memout,
                                                float* __restrict__ part) {
    __shared__ float wws[MCH*Hn];
    int b = blockIdx.x, c = blockIdx.y, t = threadIdx.x;
    ((float4*)wws)[t] = ((const float4*)(ww + (size_t)b*NWw + c*MCH*Hn))[t];
    __syncthreads();
    int h = t >> 4;
    float4 n4 = ((const float4*)nv)[b*U4 + t];
    size_t base = (size_t)(b*Mn + c*MCH)*U4 + t;
    const float4* mi = (const float4*)memin;
    float4*       mo = (float4*)memout;
    float ax=0.f, ay=0.f, az=0.f, aw=0.f;
    #pragma unroll 4
    for (int i = 0; i < MCH; i++) {
        float4 v = mi[base + (size_t)i*U4];
        float w = wws[i*Hn + h];
        float4 r;
        r.x = v.x + w*(n4.x - v.x);
        r.y = v.y + w*(n4.y - v.y);
        r.z = v.z + w*(n4.z - v.z);
        r.w = v.w + w*(n4.w - v.w);
        mo[base + (size_t)i*U4] = r;
        ax += r.x; ay += r.y; az += r.z; aw += r.w;
    }
    ((float4*)part)[(b*NCH + c)*U4 + t] = make_float4(ax, ay, az, aw);
}

__global__ __launch_bounds__(256) void k_copy(const float* __restrict__ src,
                                              float* __restrict__ dst) {
    int i = blockIdx.x*256 + threadIdx.x;
    ((float4*)dst)[i] = ((const float4*)src)[i];
}

// -------- host orchestration --------
extern "C" void kernel_launch(void* const* d_in, const int* in_sizes, int n_in,
                              void* d_out, int out_size) {
    const float* x      = (const float*)d_in[0];
    const float* mem_in = (const float*)d_in[1];
    const float* Wr     = (const float*)d_in[2];
    const float* br     = (const float*)d_in[3];
    const float* Ww     = (const float*)d_in[4];
    const float* bw     = (const float*)d_in[5];
    const float* Wk     = (const float*)d_in[6];
    const float* bk     = (const float*)d_in[7];
    float* outp    = (float*)d_out;
    float* out_mem = outp + Bn*Un;

    float *p_mem, *p_part, *p_state, *p_rlog, *p_rw, *p_wlog, *p_ww;
    float *p_read, *p_vecA, *p_vecB, *p_kpart;
    cudaGetSymbolAddress((void**)&p_mem,   g_mem);
    cudaGetSymbolAddress((void**)&p_part,  g_part);
    cudaGetSymbolAddress((void**)&p_state, g_state);
    cudaGetSymbolAddress((void**)&p_rlog,  g_rlog);
    cudaGetSymbolAddress((void**)&p_rw,    g_rw);
    cudaGetSymbolAddress((void**)&p_wlog,  g_wlog);
    cudaGetSymbolAddress((void**)&p_ww,    g_ww);
    cudaGetSymbolAddress((void**)&p_read,  g_read);
    cudaGetSymbolAddress((void**)&p_vecA,  g_vecA);
    cudaGetSymbolAddress((void**)&p_vecB,  g_vecB);
    cudaGetSymbolAddress((void**)&p_kpart, g_kpart);

    dim3 blk(256);
    const float* cur_mem = mem_in;
    const float* cur_out = x;

    // initial memstate (only full slot-sum pass of the whole run)
    k_slotsum<<<dim3(Bn, NCH), blk>>>(cur_mem, p_part);
    k_state_fin<<<Bn, blk>>>(p_part, cur_out, p_state);

    for (int l = 0; l < Dn; l++) {
        float* nv = (l & 1) ? p_vecB : p_vecA;

        // read logits + softmax
        k_gemm<<<dim3(129, 1, 1), blk>>>(p_state, Wr + (size_t)l*Un*NRr, p_rlog, NRr, 1024);
        k_softmax<NSLOT, NRr><<<128, blk>>>(p_rlog, br + (size_t)l*NRr, p_rw);

        // weighted read over memory (+input slot)
        k_wread<<<dim3(Bn, NCH), blk>>>(cur_mem, p_rw, p_part);
        k_read_fin<<<Bn, blk>>>(p_part, cur_out, p_rw, p_read);

        // newval = relu(read @ Wk + bk)   (K-split x4 for SM occupancy)
        k_gemm<<<dim3(16, 1, 4), blk>>>(p_read, Wk + (size_t)l*Un*Un, p_kpart, Un, 256);
        k_wk_reduce<<<Bn, blk>>>(p_kpart, bk + (size_t)l*Un, nv);

        // write logits + softmax
        k_gemm<<<dim3(128, 1, 1), blk>>>(nv, Ww + (size_t)l*Un*NWw, p_wlog, NWw, 1024);
        k_softmax<Mn, NWw><<<128, blk>>>(p_wlog, bw + (size_t)l*NWw, p_ww);

        // memory update, fused with next layer's slot-sum partials
        float* dst = (l == Dn - 1) ? out_mem : p_mem;
        k_update<<<dim3(Bn, NCH), blk>>>(cur_mem, p_ww, nv, dst, p_part);
        if (l < Dn - 1) k_state_fin<<<Bn, blk>>>(p_part, nv, p_state);

        cur_mem = dst;
        cur_out = nv;
    }

    k_copy<<<Bn, blk>>>(cur_out, outp);   // final out = newval of layer 3
}

// round 2
// speedup vs baseline: 1.6305x; 1.6305x over previous
#include <cuda_runtime.h>
#include <cuda_bf16.h>
#include <math.h>
#include <stdint.h>

// Problem constants
#define Bn 64
#define Un 1024
#define Hn 16
#define Mn 512
#define Dn 4
#define NSLOT 513
#define NRr 8208             // H*(M+1)
#define NWw 8192             // H*M
#define U4 256               // U/4
#define MCH 64               // slots per pass-block
#define NCH 8                // M / MCH
#define SLP 520              // padded slot stride for transposed logits/probs

// -------- scratch (device globals; no runtime allocation) --------
__device__ float g_mem  [Bn*Mn*Un];
__device__ float g_part [Bn*NCH*Un];
__device__ float g_state[Bn*Un];
__device__ float g_rlogT[Bn*Hn*SLP];   // [b][h][slot]
__device__ float g_rwT  [Bn*Hn*SLP];
__device__ float g_wlogT[Bn*Hn*SLP];
__device__ float g_wwT  [Bn*Hn*SLP];
__device__ float g_read [Bn*Un];
__device__ float g_vecA [Bn*Un];
__device__ float g_vecB [Bn*Un];
__device__ float g_kpart[4*Bn*Un];

// -------- small helpers --------
static __device__ __forceinline__ uint32_t smem_u32(const void* p) {
    return (uint32_t)__cvta_generic_to_shared(p);
}
static __device__ __forceinline__ uint32_t pk2(float a, float b) {
    __nv_bfloat162 t = __floats2bfloat162_rn(a, b);
    return *reinterpret_cast<uint32_t*>(&t);
}
static __device__ __forceinline__ void ldsm4(uint32_t r[4], uint32_t addr) {
    asm volatile("ldmatrix.sync.aligned.m8n8.x4.shared.b16 {%0,%1,%2,%3}, [%4];"
                 : "=r"(r[0]), "=r"(r[1]), "=r"(r[2]), "=r"(r[3]) : "r"(addr));
}
static __device__ __forceinline__ void ldsm4t(uint32_t r[4], uint32_t addr) {
    asm volatile("ldmatrix.sync.aligned.m8n8.x4.trans.shared.b16 {%0,%1,%2,%3}, [%4];"
                 : "=r"(r[0]), "=r"(r[1]), "=r"(r[2]), "=r"(r[3]) : "r"(addr));
}
static __device__ __forceinline__ void mma16816(float c[4], const uint32_t a[4],
                                                uint32_t b0, uint32_t b1) {
    asm volatile("mma.sync.aligned.m16n8k16.row.col.f32.bf16.bf16.f32 "
                 "{%0,%1,%2,%3}, {%4,%5,%6,%7}, {%8,%9}, {%0,%1,%2,%3};"
                 : "+f"(c[0]), "+f"(c[1]), "+f"(c[2]), "+f"(c[3])
                 : "r"(a[0]), "r"(a[1]), "r"(a[2]), "r"(a[3]), "r"(b0), "r"(b1));
}

// -------- bf16 tensor-core GEMM: C[64 x N] = A[64x1024] @ W[1024 x N] --------
// Epilogue writes TRANSPOSED: dstT[(b*16 + n%16)*SLP + n/16] (logit layout [b][h][slot]).
// One CTA computes a 64x64 C tile over full K=1024. fp32->bf16 conversion on the fly.
__global__ __launch_bounds__(256) void k_gemm_bf16T(const float* __restrict__ A,
                                                    const float* __restrict__ W,
                                                    float* __restrict__ dstT,
                                                    int N) {
    __shared__ uint4 Asm[2][512];   // [buf][row*8 + swizzled 16B chunk]
    __shared__ uint4 Bsm[2][512];
    const int t = threadIdx.x;
    const int n0 = blockIdx.x * 64;
    const int lane = t & 31, w = t >> 5;
    const int m0 = (w & 3) * 16;        // warp m offset (C is 64 rows)
    const int nw0 = (w >> 2) * 32;      // warp n offset within tile

    const uint32_t aBase = smem_u32(Asm);
    const uint32_t bBase = smem_u32(Bsm);

    float acc[4][4];
    #pragma unroll
    for (int j = 0; j < 4; j++)
        #pragma unroll
        for (int r = 0; r < 4; r++) acc[j][r] = 0.f;

    float4 ra[2][2], rb[2][2];

    auto loadStage = [&](int k0) {
        #pragma unroll
        for (int it = 0; it < 2; it++) {
            int idx = t + 256 * it;
            int r = idx >> 3, c = idx & 7;
            // A tile row r = batch m, cols k0+c*8..+7  (always in-bounds)
            const float* ap = A + r * Un + k0 + c * 8;
            ra[it][0] = *(const float4*)ap;
            ra[it][1] = *(const float4*)(ap + 4);
            // B tile row r = k, cols n0+c*8..+7 of W (guard N)
            int n = n0 + c * 8;
            const float* wp = W + (size_t)(k0 + r) * N + n;
            if (n + 7 < N) {
                rb[it][0] = *(const float4*)wp;
                rb[it][1] = *(const float4*)(wp + 4);
            } else {
                float v[8];
                #pragma unroll
                for (int j = 0; j < 8; j++) v[j] = (n + j < N) ? wp[j] : 0.f;
                rb[it][0] = make_float4(v[0], v[1], v[2], v[3]);
                rb[it][1] = make_float4(v[4], v[5], v[6], v[7]);
            }
        }
    };
    auto stsStage = [&](int buf) {
        #pragma unroll
        for (int it = 0; it < 2; it++) {
            int idx = t + 256 * it;
            int r = idx >> 3, c = idx & 7;
            int u = r * 8 + (c ^ (r & 7));
            Asm[buf][u] = make_uint4(pk2(ra[it][0].x, ra[it][0].y), pk2(ra[it][0].z, ra[it][0].w),
                                     pk2(ra[it][1].x, ra[it][1].y), pk2(ra[it][1].z, ra[it][1].w));
            Bsm[buf][u] = make_uint4(pk2(rb[it][0].x, rb[it][0].y), pk2(rb[it][0].z, rb[it][0].w),
                                     pk2(rb[it][1].x, rb[it][1].y), pk2(rb[it][1].z, rb[it][1].w));
        }
    };

    loadStage(0);
    stsStage(0);
    __syncthreads();

    for (int ch = 0; ch < 16; ch++) {
        if (ch < 15) loadStage((ch + 1) * 64);
        const int buf = ch & 1;
        const uint32_t aB = aBase + buf * 8192;
        const uint32_t bB = bBase + buf * 8192;
        #pragma unroll
        for (int ksi = 0; ksi < 4; ksi++) {
            const int ks = ksi * 16;
            uint32_t af[4], bf0[4], bf1[4];
            {
                int r = m0 + (lane & 15), c = (ks >> 3) + (lane >> 4);
                ldsm4(af, aB + (uint32_t)(r * 8 + (c ^ (r & 7))) * 16);
            }
            {
                int r = ks + (lane & 15), c = (nw0 >> 3) + (lane >> 4);
                ldsm4t(bf0, bB + (uint32_t)(r * 8 + (c ^ (r & 7))) * 16);
            }
            {
                int r = ks + (lane & 15), c = ((nw0 + 16) >> 3) + (lane >> 4);
                ldsm4t(bf1, bB + (uint32_t)(r * 8 + (c ^ (r & 7))) * 16);
            }
            mma16816(acc[0], af, bf0[0], bf0[1]);
            mma16816(acc[1], af, bf0[2], bf0[3]);
            mma16816(acc[2], af, bf1[0], bf1[1]);
            mma16816(acc[3], af, bf1[2], bf1[3]);
        }
        if (ch < 15) stsStage(buf ^ 1);
        __syncthreads();
    }

    // epilogue: transposed scatter into [b][h][slot]
    const int g = lane >> 2, tg = lane & 3;
    #pragma unroll
    for (int j = 0; j < 4; j++) {
        int ncol = n0 + nw0 + j * 8 + tg * 2;
        int m_lo = m0 + g, m_hi = m0 + g + 8;
        #pragma unroll
        for (int e = 0; e < 2; e++) {
            int n = ncol + e;
            if (n < N) {
                int h = n & 15, s = n >> 4;
                dstT[(size_t)(m_lo * Hn + h) * SLP + s] = acc[j][e];
                dstT[(size_t)(m_hi * Hn + h) * SLP + s] = acc[j][2 + e];
            }
        }
    }
}

// -------- fp32 GEMM (kept for Wk: precision-critical path) --------
__global__ __launch_bounds__(256) void k_gemm(const float* __restrict__ A,
                                              const float* __restrict__ W,
                                              float* __restrict__ C,
                                              int N, int Ksub) {
    __shared__ float As[32][68];
    __shared__ float Ws[32][64];
    int t  = threadIdx.x;
    int j0 = blockIdx.x * 64;
    int kb = blockIdx.z * Ksub;
    int rg = t >> 4, cg = t & 15;
    float acc[4][4];
    #pragma unroll
    for (int r = 0; r < 4; r++)
        #pragma unroll
        for (int c = 0; c < 4; c++) acc[r][c] = 0.f;

    for (int k0 = kb; k0 < kb + Ksub; k0 += 32) {
        #pragma unroll
        for (int r = 0; r < 8; r++) {
            int idx = t + 256*r;
            int i = idx >> 5, k = idx & 31;
            As[k][i] = A[i*Un + k0 + k];
        }
        #pragma unroll
        for (int r = 0; r < 8; r++) {
            int idx = t + 256*r;
            int k = idx >> 6, j = idx & 63;
            int gj = j0 + j;
            Ws[k][j] = (gj < N) ? W[(size_t)(k0 + k)*N + gj] : 0.f;
        }
        __syncthreads();
        #pragma unroll
        for (int k = 0; k < 32; k++) {
            float4 a = *(const float4*)&As[k][rg*4];
            float4 wv = *(const float4*)&Ws[k][cg*4];
            acc[0][0] += a.x*wv.x; acc[0][1] += a.x*wv.y; acc[0][2] += a.x*wv.z; acc[0][3] += a.x*wv.w;
            acc[1][0] += a.y*wv.x; acc[1][1] += a.y*wv.y; acc[1][2] += a.y*wv.z; acc[1][3] += a.y*wv.w;
            acc[2][0] += a.z*wv.x; acc[2][1] += a.z*wv.y; acc[2][2] += a.z*wv.z; acc[2][3] += a.z*wv.w;
            acc[3][0] += a.w*wv.x; acc[3][1] += a.w*wv.y; acc[3][2] += a.w*wv.z; acc[3][3] += a.w*wv.w;
        }
        __syncthreads();
    }
    size_t zo = (size_t)blockIdx.z * 64 * N;
    #pragma unroll
    for (int r = 0; r < 4; r++) {
        int i = rg*4 + r;
        #pragma unroll
        for (int c = 0; c < 4; c++) {
            int j = j0 + cg*4 + c;
            if (j < N) C[zo + (size_t)i*N + j] = acc[r][c];
        }
    }
}

// -------- transposed softmax: warp per (b,h), contiguous slot reads --------
template <int NS>
__global__ __launch_bounds__(256) void k_softmaxT(const float* __restrict__ logitT,
                                                  const float* __restrict__ bias,
                                                  float* __restrict__ probT) {
    constexpr int IT = (NS + 31) / 32;
    int gw = (blockIdx.x * 256 + threadIdx.x) >> 5;
    int lane = threadIdx.x & 31;
    int h = gw & 15;
    const float* base = logitT + (size_t)gw * SLP;
    float vals[IT];
    float mx = -1e30f;
    #pragma unroll
    for (int i = 0; i < IT; i++) {
        int s = i * 32 + lane;
        float v = -1e30f;
        if (s < NS) v = base[s] + bias[s * Hn + h];
        vals[i] = v;
        mx = fmaxf(mx, v);
    }
    #pragma unroll
    for (int o = 16; o; o >>= 1) mx = fmaxf(mx, __shfl_xor_sync(0xffffffffu, mx, o));
    float sum = 0.f;
    #pragma unroll
    for (int i = 0; i < IT; i++) {
        int s = i * 32 + lane;
        float e = (s < NS) ? __expf(vals[i] - mx) : 0.f;
        vals[i] = e;
        sum += e;
    }
    #pragma unroll
    for (int o = 16; o; o >>= 1) sum += __shfl_xor_sync(0xffffffffu, sum, o);
    float inv = 1.f / sum;
    float* dst = probT + (size_t)gw * SLP;
    #pragma unroll
    for (int i = 0; i < IT; i++) {
        int s = i * 32 + lane;
        if (s < NS) dst[s] = vals[i] * inv;
    }
}

// -------- memory passes --------
__global__ __launch_bounds__(256) void k_slotsum(const float* __restrict__ mem,
                                                 float* __restrict__ part) {
    int b = blockIdx.x, c = blockIdx.y, t = threadIdx.x;
    const float4* m4 = (const float4*)mem + (size_t)(b*Mn + c*MCH)*U4 + t;
    float ax=0.f, ay=0.f, az=0.f, aw=0.f;
    #pragma unroll 8
    for (int i = 0; i < MCH; i++) {
        float4 v = m4[(size_t)i*U4];
        ax += v.x; ay += v.y; az += v.z; aw += v.w;
    }
    ((float4*)part)[(b*NCH + c)*U4 + t] = make_float4(ax, ay, az, aw);
}

__global__ __launch_bounds__(256) void k_state_fin(const float* __restrict__ part,
                                                   const float* __restrict__ vec,
                                                   float* __restrict__ state) {
    int b = blockIdx.x, t = threadIdx.x;
    float4 a = ((const float4*)vec)[b*U4 + t];
    #pragma unroll
    for (int c = 0; c < NCH; c++) {
        float4 v = ((const float4*)part)[(b*NCH + c)*U4 + t];
        a.x += v.x; a.y += v.y; a.z += v.z; a.w += v.w;
    }
    const float inv = 1.f / 513.f;
    a.x *= inv; a.y *= inv; a.z *= inv; a.w *= inv;
    ((float4*)state)[b*U4 + t] = a;
}

// weighted read with transposed probs rwT[b][h][slot]
__global__ __launch_bounds__(256) void k_wread(const float* __restrict__ mem,
                                               const float* __restrict__ rwT,
                                               float* __restrict__ part) {
    __shared__ float rws[MCH][17];
    int b = blockIdx.x, c = blockIdx.y, t = threadIdx.x;
    #pragma unroll
    for (int it = 0; it < 4; it++) {
        int idx = t + 256 * it;
        int hh = idx >> 6, s = idx & 63;
        rws[s][hh] = rwT[(size_t)(b*Hn + hh)*SLP + c*MCH + s];
    }
    __syncthreads();
    int h = t >> 4;
    const float4* m4 = (const float4*)mem + (size_t)(b*Mn + c*MCH)*U4 + t;
    float ax=0.f, ay=0.f, az=0.f, aw=0.f;
    #pragma unroll 8
    for (int i = 0; i < MCH; i++) {
        float4 v = m4[(size_t)i*U4];
        float wv = rws[i][h];
        ax += wv*v.x; ay += wv*v.y; az += wv*v.z; aw += wv*v.w;
    }
    ((float4*)part)[(b*NCH + c)*U4 + t] = make_float4(ax, ay, az, aw);
}

__global__ __launch_bounds__(256) void k_read_fin(const float* __restrict__ part,
                                                  const float* __restrict__ outv,
                                                  const float* __restrict__ rwT,
                                                  float* __restrict__ readv) {
    int b = blockIdx.x, t = threadIdx.x;
    int h = t >> 4;
    float wl = rwT[(size_t)(b*Hn + h)*SLP + Mn];   // input slot (index M)
    float4 a = ((const float4*)outv)[b*U4 + t];
    a.x *= wl; a.y *= wl; a.z *= wl; a.w *= wl;
    #pragma unroll
    for (int c = 0; c < NCH; c++) {
        float4 v = ((const float4*)part)[(b*NCH + c)*U4 + t];
        a.x += v.x; a.y += v.y; a.z += v.z; a.w += v.w;
    }
    ((float4*)readv)[b*U4 + t] = a;
}

__global__ __launch_bounds__(256) void k_wk_reduce(const float* __restrict__ part,
                                                   const float* __restrict__ bk,
                                                   float* __restrict__ nv) {
    int b = blockIdx.x, t = threadIdx.x;
    float4 a = ((const float4*)bk)[t];
    #pragma unroll
    for (int z = 0; z < 4; z++) {
        float4 v = ((const float4*)part)[((size_t)z*Bn + b)*U4 + t];
        a.x += v.x; a.y += v.y; a.z += v.z; a.w += v.w;
    }
    a.x = fmaxf(a.x, 0.f); a.y = fmaxf(a.y, 0.f);
    a.z = fmaxf(a.z, 0.f); a.w = fmaxf(a.w, 0.f);
    ((float4*)nv)[b*U4 + t] = a;
}

// mem' = (1-ww)*mem + ww*newval with transposed wwT; fused next-layer slot-sum partials
__global__ __launch_bounds__(256) void k_update(const float* __restrict__ memin,
                                                const float* __restrict__ wwT,
                                                const float* __restrict__ nv,
                                                float* __restrict__ memout,
                                                float* __restrict__ part) {
    __shared__ float wws[MCH][17];
    int b = blockIdx.x, c = blockIdx.y, t = threadIdx.x;
    #pragma unroll
    for (int it = 0; it < 4; it++) {
        int idx = t + 256 * it;
        int hh = idx >> 6, s = idx & 63;
        wws[s][hh] = wwT[(size_t)(b*Hn + hh)*SLP + c*MCH + s];
    }
    __syncthreads();
    int h = t >> 4;
    float4 n4 = ((const float4*)nv)[b*U4 + t];
    size_t base = (size_t)(b*Mn + c*MCH)*U4 + t;
    const float4* mi = (const float4*)memin;
    float4*       mo = (float4*)memout;
    float ax=0.f, ay=0.f, az=0.f, aw=0.f;
    #pragma unroll 8
    for (int i = 0; i < MCH; i++) {
        float4 v = mi[base + (size_t)i*U4];
        float wv = wws[i][h];
        float4 r;
        r.x = v.x + wv*(n4.x - v.x);
        r.y = v.y + wv*(n4.y - v.y);
        r.z = v.z + wv*(n4.z - v.z);
        r.w = v.w + wv*(n4.w - v.w);
        mo[base + (size_t)i*U4] = r;
        ax += r.x; ay += r.y; az += r.z; aw += r.w;
    }
    ((float4*)part)[(b*NCH + c)*U4 + t] = make_float4(ax, ay, az, aw);
}

__global__ __launch_bounds__(256) void k_copy(const float* __restrict__ src,
                                              float* __restrict__ dst) {
    int i = blockIdx.x*256 + threadIdx.x;
    ((float4*)dst)[i] = ((const float4*)src)[i];
}

// -------- host orchestration --------
extern "C" void kernel_launch(void* const* d_in, const int* in_sizes, int n_in,
                              void* d_out, int out_size) {
    const float* x      = (const float*)d_in[0];
    const float* mem_in = (const float*)d_in[1];
    const float* Wr     = (const float*)d_in[2];
    const float* br     = (const float*)d_in[3];
    const float* Ww     = (const float*)d_in[4];
    const float* bw     = (const float*)d_in[5];
    const float* Wk     = (const float*)d_in[6];
    const float* bk     = (const float*)d_in[7];
    float* outp    = (float*)d_out;
    float* out_mem = outp + Bn*Un;

    float *p_mem, *p_part, *p_state, *p_rlogT, *p_rwT, *p_wlogT, *p_wwT;
    float *p_read, *p_vecA, *p_vecB, *p_kpart;
    cudaGetSymbolAddress((void**)&p_mem,    g_mem);
    cudaGetSymbolAddress((void**)&p_part,   g_part);
    cudaGetSymbolAddress((void**)&p_state,  g_state);
    cudaGetSymbolAddress((void**)&p_rlogT,  g_rlogT);
    cudaGetSymbolAddress((void**)&p_rwT,    g_rwT);
    cudaGetSymbolAddress((void**)&p_wlogT,  g_wlogT);
    cudaGetSymbolAddress((void**)&p_wwT,    g_wwT);
    cudaGetSymbolAddress((void**)&p_read,   g_read);
    cudaGetSymbolAddress((void**)&p_vecA,   g_vecA);
    cudaGetSymbolAddress((void**)&p_vecB,   g_vecB);
    cudaGetSymbolAddress((void**)&p_kpart,  g_kpart);

    dim3 blk(256);
    const float* cur_mem = mem_in;
    const float* cur_out = x;

    // initial memstate
    k_slotsum<<<dim3(Bn, NCH), blk>>>(cur_mem, p_part);
    k_state_fin<<<Bn, blk>>>(p_part, cur_out, p_state);

    for (int l = 0; l < Dn; l++) {
        float* nv = (l & 1) ? p_vecB : p_vecA;

        // read logits (bf16 tensor cores, transposed out) + softmax
        k_gemm_bf16T<<<129, blk>>>(p_state, Wr + (size_t)l*Un*NRr, p_rlogT, NRr);
        k_softmaxT<NSLOT><<<128, blk>>>(p_rlogT, br + (size_t)l*NRr, p_rwT);

        // weighted read over memory (+input slot)
        k_wread<<<dim3(Bn, NCH), blk>>>(cur_mem, p_rwT, p_part);
        k_read_fin<<<Bn, blk>>>(p_part, cur_out, p_rwT, p_read);

        // newval = relu(read @ Wk + bk)  — fp32 path for output precision
        k_gemm<<<dim3(16, 1, 4), blk>>>(p_read, Wk + (size_t)l*Un*Un, p_kpart, Un, 256);
        k_wk_reduce<<<Bn, blk>>>(p_kpart, bk + (size_t)l*Un, nv);

        // write logits (bf16 tensor cores) + softmax
        k_gemm_bf16T<<<128, blk>>>(nv, Ww + (size_t)l*Un*NWw, p_wlogT, NWw);
        k_softmaxT<Mn><<<128, blk>>>(p_wlogT, bw + (size_t)l*NWw, p_wwT);

        // memory update fused with next layer's slot-sum partials
        float* dst = (l == Dn - 1) ? out_mem : p_mem;
        k_update<<<dim3(Bn, NCH), blk>>>(cur_mem, p_wwT, nv, dst, p_part);
        if (l < Dn - 1) k_state_fin<<<Bn, blk>>>(p_part, nv, p_state);

        cur_mem = dst;
        cur_out = nv;
    }

    k_copy<<<Bn, blk>>>(cur_out, outp);
}

// round 3
// speedup vs baseline: 1.8412x; 1.1292x over previous
#include <cuda_runtime.h>
#include <cuda_bf16.h>
#include <math.h>
#include <stdint.h>

// Problem constants
#define Bn 64
#define Un 1024
#define Hn 16
#define Mn 512
#define Dn 4
#define NSLOT 513
#define NRr 8208             // H*(M+1)
#define NWw 8192             // H*M
#define U4 256               // U/4
#define MCH 64               // slots per pass-block
#define NCH 8                // M / MCH
#define SLP 520              // padded slot stride for transposed logits/probs
#define BHR 512              // per-(b,h) row stride for coeff arrays
#define BSTR 524288          // per-j stride of B coeff array (64*16*512)
#define NV4 16384            // float4 stride of one nv buffer (65536/4)

// -------- scratch (device globals) --------
__device__ float g_part [Bn*NCH*Un];     // per-chunk partials (reused)
__device__ float g_S    [Bn*Un];         // running S = sum_m A*mem0
__device__ float g_state[Bn*Un];
__device__ float g_rlogT[Bn*Hn*SLP];
__device__ float g_rwT  [Bn*Hn*SLP];
__device__ float g_wlogT[Bn*Hn*SLP];
__device__ float g_wwT  [Bn*Hn*SLP];
__device__ float g_read [Bn*Un];
__device__ float g_nv   [4*Bn*Un];       // newval per layer
__device__ float g_kpart[4*Bn*Un];       // K-split partials for Wk GEMM
__device__ float g_A    [Bn*Hn*BHR];     // A coeff  [b][h][m]
__device__ float g_wA   [Bn*Hn*BHR];     // A_{l-1}*ww_l (T-pass weights)
__device__ float g_B    [4*Bn*Hn*BHR];   // B coeffs [j][b][h][m]
__device__ float g_sB   [4*Bn*Hn];       // per-(b,h) sums of B_j

// -------- helpers --------
static __device__ __forceinline__ uint32_t smem_u32(const void* p) {
    return (uint32_t)__cvta_generic_to_shared(p);
}
static __device__ __forceinline__ uint32_t pk2(float a, float b) {
    __nv_bfloat162 t = __floats2bfloat162_rn(a, b);
    return *reinterpret_cast<uint32_t*>(&t);
}
static __device__ __forceinline__ void split_pk(float x, float y, uint32_t& hi, uint32_t& lo) {
    __nv_bfloat16 hx = __float2bfloat16(x);
    __nv_bfloat16 hy = __float2bfloat16(y);
    __nv_bfloat162 h2; h2.x = hx; h2.y = hy;
    hi = *reinterpret_cast<uint32_t*>(&h2);
    __nv_bfloat162 l2 = __floats2bfloat162_rn(x - __bfloat162float(hx),
                                              y - __bfloat162float(hy));
    lo = *reinterpret_cast<uint32_t*>(&l2);
}
static __device__ __forceinline__ void ldsm4(uint32_t r[4], uint32_t addr) {
    asm volatile("ldmatrix.sync.aligned.m8n8.x4.shared.b16 {%0,%1,%2,%3}, [%4];"
                 : "=r"(r[0]), "=r"(r[1]), "=r"(r[2]), "=r"(r[3]) : "r"(addr));
}
static __device__ __forceinline__ void ldsm4t(uint32_t r[4], uint32_t addr) {
    asm volatile("ldmatrix.sync.aligned.m8n8.x4.trans.shared.b16 {%0,%1,%2,%3}, [%4];"
                 : "=r"(r[0]), "=r"(r[1]), "=r"(r[2]), "=r"(r[3]) : "r"(addr));
}
static __device__ __forceinline__ void mma16816(float c[4], const uint32_t a[4],
                                                uint32_t b0, uint32_t b1) {
    asm volatile("mma.sync.aligned.m16n8k16.row.col.f32.bf16.bf16.f32 "
                 "{%0,%1,%2,%3}, {%4,%5,%6,%7}, {%8,%9}, {%0,%1,%2,%3};"
                 : "+f"(c[0]), "+f"(c[1]), "+f"(c[2]), "+f"(c[3])
                 : "r"(a[0]), "r"(a[1]), "r"(a[2]), "r"(a[3]), "r"(b0), "r"(b1));
}

// -------- bf16 TC GEMM with transposed epilogue + fused bias --------
__global__ __launch_bounds__(256) void k_gemm_bf16T(const float* __restrict__ A,
                                                    const float* __restrict__ W,
                                                    const float* __restrict__ bias,
                                                    float* __restrict__ dstT,
                                                    int N) {
    __shared__ uint4 Asm[2][512];
    __shared__ uint4 Bsm[2][512];
    const int t = threadIdx.x;
    const int n0 = blockIdx.x * 64;
    const int lane = t & 31, w = t >> 5;
    const int m0 = (w & 3) * 16;
    const int nw0 = (w >> 2) * 32;
    const uint32_t aBase = smem_u32(Asm);
    const uint32_t bBase = smem_u32(Bsm);

    float acc[4][4];
    #pragma unroll
    for (int j = 0; j < 4; j++)
        #pragma unroll
        for (int r = 0; r < 4; r++) acc[j][r] = 0.f;

    float4 ra[2][2], rb[2][2];
    auto loadStage = [&](int k0) {
        #pragma unroll
        for (int it = 0; it < 2; it++) {
            int idx = t + 256 * it;
            int r = idx >> 3, c = idx & 7;
            const float* ap = A + r * Un + k0 + c * 8;
            ra[it][0] = *(const float4*)ap;
            ra[it][1] = *(const float4*)(ap + 4);
            int n = n0 + c * 8;
            const float* wp = W + (size_t)(k0 + r) * N + n;
            if (n + 7 < N) {
                rb[it][0] = *(const float4*)wp;
                rb[it][1] = *(const float4*)(wp + 4);
            } else {
                float v[8];
                #pragma unroll
                for (int j = 0; j < 8; j++) v[j] = (n + j < N) ? wp[j] : 0.f;
                rb[it][0] = make_float4(v[0], v[1], v[2], v[3]);
                rb[it][1] = make_float4(v[4], v[5], v[6], v[7]);
            }
        }
    };
    auto stsStage = [&](int buf) {
        #pragma unroll
        for (int it = 0; it < 2; it++) {
            int idx = t + 256 * it;
            int r = idx >> 3, c = idx & 7;
            int u = r * 8 + (c ^ (r & 7));
            Asm[buf][u] = make_uint4(pk2(ra[it][0].x, ra[it][0].y), pk2(ra[it][0].z, ra[it][0].w),
                                     pk2(ra[it][1].x, ra[it][1].y), pk2(ra[it][1].z, ra[it][1].w));
            Bsm[buf][u] = make_uint4(pk2(rb[it][0].x, rb[it][0].y), pk2(rb[it][0].z, rb[it][0].w),
                                     pk2(rb[it][1].x, rb[it][1].y), pk2(rb[it][1].z, rb[it][1].w));
        }
    };

    loadStage(0);
    stsStage(0);
    __syncthreads();

    for (int ch = 0; ch < 16; ch++) {
        if (ch < 15) loadStage((ch + 1) * 64);
        const int buf = ch & 1;
        const uint32_t aB = aBase + buf * 8192;
        const uint32_t bB = bBase + buf * 8192;
        #pragma unroll
        for (int ksi = 0; ksi < 4; ksi++) {
            const int ks = ksi * 16;
            uint32_t af[4], bf0[4], bf1[4];
            { int r = m0 + (lane & 15), c = (ks >> 3) + (lane >> 4);
              ldsm4(af, aB + (uint32_t)(r * 8 + (c ^ (r & 7))) * 16); }
            { int r = ks + (lane & 15), c = (nw0 >> 3) + (lane >> 4);
              ldsm4t(bf0, bB + (uint32_t)(r * 8 + (c ^ (r & 7))) * 16); }
            { int r = ks + (lane & 15), c = ((nw0 + 16) >> 3) + (lane >> 4);
              ldsm4t(bf1, bB + (uint32_t)(r * 8 + (c ^ (r & 7))) * 16); }
            mma16816(acc[0], af, bf0[0], bf0[1]);
            mma16816(acc[1], af, bf0[2], bf0[3]);
            mma16816(acc[2], af, bf1[0], bf1[1]);
            mma16816(acc[3], af, bf1[2], bf1[3]);
        }
        if (ch < 15) stsStage(buf ^ 1);
        __syncthreads();
    }

    const int g = lane >> 2, tg = lane & 3;
    #pragma unroll
    for (int j = 0; j < 4; j++) {
        int ncol = n0 + nw0 + j * 8 + tg * 2;
        int m_lo = m0 + g, m_hi = m0 + g + 8;
        #pragma unroll
        for (int e = 0; e < 2; e++) {
            int n = ncol + e;
            if (n < N) {
                float bv = bias[n];
                int h = n & 15, s = n >> 4;
                dstT[(size_t)(m_lo * Hn + h) * SLP + s] = acc[j][e] + bv;
                dstT[(size_t)(m_hi * Hn + h) * SLP + s] = acc[j][2 + e] + bv;
            }
        }
    }
}

// -------- bf16x3 split-precision GEMM for Wk (fp32-quality) --------
// grid (16 ntiles, 1, 4 zsplits); C z-partials into kpart, row-major.
__global__ __launch_bounds__(256) void k_gemm_x3(const float* __restrict__ A,
                                                 const float* __restrict__ W,
                                                 float* __restrict__ kpart) {
    __shared__ uint4 S4[4][512];    // 0:Ahi 1:Alo 2:Bhi 3:Blo
    const int t = threadIdx.x;
    const int n0 = blockIdx.x * 64;
    const int kb = blockIdx.z * 256;
    const int lane = t & 31, w = t >> 5;
    const int m0 = (w & 3) * 16;
    const int nw0 = (w >> 2) * 32;
    const uint32_t base = smem_u32(S4);

    float acc[4][4];
    #pragma unroll
    for (int j = 0; j < 4; j++)
        #pragma unroll
        for (int r = 0; r < 4; r++) acc[j][r] = 0.f;

    for (int ch = 0; ch < 4; ch++) {
        int k0 = kb + ch * 64;
        float4 ra[2][2], rb[2][2];
        #pragma unroll
        for (int it = 0; it < 2; it++) {
            int idx = t + 256 * it;
            int r = idx >> 3, c = idx & 7;
            const float* ap = A + r * Un + k0 + c * 8;
            ra[it][0] = *(const float4*)ap;
            ra[it][1] = *(const float4*)(ap + 4);
            const float* wp = W + (size_t)(k0 + r) * Un + n0 + c * 8;
            rb[it][0] = *(const float4*)wp;
            rb[it][1] = *(const float4*)(wp + 4);
        }
        __syncthreads();   // prior compute done before overwrite
        #pragma unroll
        for (int it = 0; it < 2; it++) {
            int idx = t + 256 * it;
            int r = idx >> 3, c = idx & 7;
            int u = r * 8 + (c ^ (r & 7));
            uint32_t h0,l0,h1,l1,h2,l2,h3,l3;
            split_pk(ra[it][0].x, ra[it][0].y, h0, l0);
            split_pk(ra[it][0].z, ra[it][0].w, h1, l1);
            split_pk(ra[it][1].x, ra[it][1].y, h2, l2);
            split_pk(ra[it][1].z, ra[it][1].w, h3, l3);
            S4[0][u] = make_uint4(h0, h1, h2, h3);
            S4[1][u] = make_uint4(l0, l1, l2, l3);
            split_pk(rb[it][0].x, rb[it][0].y, h0, l0);
            split_pk(rb[it][0].z, rb[it][0].w, h1, l1);
            split_pk(rb[it][1].x, rb[it][1].y, h2, l2);
            split_pk(rb[it][1].z, rb[it][1].w, h3, l3);
            S4[2][u] = make_uint4(h0, h1, h2, h3);
            S4[3][u] = make_uint4(l0, l1, l2, l3);
        }
        __syncthreads();
        #pragma unroll
        for (int ksi = 0; ksi < 4; ksi++) {
            const int ks = ksi * 16;
            uint32_t ah[4], al[4], bh0[4], bh1[4], bl0[4], bl1[4];
            int ra_ = m0 + (lane & 15), ca = (ks >> 3) + (lane >> 4);
            uint32_t aoff = (uint32_t)(ra_ * 8 + (ca ^ (ra_ & 7))) * 16;
            ldsm4(ah, base + aoff);
            ldsm4(al, base + 8192 + aoff);
            int rb_ = ks + (lane & 15);
            int cb0 = (nw0 >> 3) + (lane >> 4), cb1 = ((nw0 + 16) >> 3) + (lane >> 4);
            uint32_t b0off = (uint32_t)(rb_ * 8 + (cb0 ^ (rb_ & 7))) * 16;
            uint32_t b1off = (uint32_t)(rb_ * 8 + (cb1 ^ (rb_ & 7))) * 16;
            ldsm4t(bh0, base + 16384 + b0off);
            ldsm4t(bh1, base + 16384 + b1off);
            ldsm4t(bl0, base + 24576 + b0off);
            ldsm4t(bl1, base + 24576 + b1off);
            // hi*hi + hi*lo + lo*hi
            mma16816(acc[0], ah, bh0[0], bh0[1]);
            mma16816(acc[0], ah, bl0[0], bl0[1]);
            mma16816(acc[0], al, bh0[0], bh0[1]);
            mma16816(acc[1], ah, bh0[2], bh0[3]);
            mma16816(acc[1], ah, bl0[2], bl0[3]);
            mma16816(acc[1], al, bh0[2], bh0[3]);
            mma16816(acc[2], ah, bh1[0], bh1[1]);
            mma16816(acc[2], ah, bl1[0], bl1[1]);
            mma16816(acc[2], al, bh1[0], bh1[1]);
            mma16816(acc[3], ah, bh1[2], bh1[3]);
            mma16816(acc[3], ah, bl1[2], bl1[3]);
            mma16816(acc[3], al, bh1[2], bh1[3]);
        }
    }
    size_t zo = (size_t)blockIdx.z * Bn * Un;
    const int g = lane >> 2, tg = lane & 3;
    #pragma unroll
    for (int j = 0; j < 4; j++) {
        int ncol = n0 + nw0 + j * 8 + tg * 2;
        int m_lo = m0 + g, m_hi = m0 + g + 8;
        *(float2*)&kpart[zo + (size_t)m_lo * Un + ncol] = make_float2(acc[j][0], acc[j][1]);
        *(float2*)&kpart[zo + (size_t)m_hi * Un + ncol] = make_float2(acc[j][2], acc[j][3]);
    }
}

// -------- softmax over contiguous rows (bias pre-fused in GEMM) --------
template <int NS>
__global__ __launch_bounds__(256) void k_softmaxT(const float* __restrict__ logitT,
                                                  float* __restrict__ probT) {
    constexpr int IT = (NS + 31) / 32;
    int gw = (blockIdx.x * 256 + threadIdx.x) >> 5;
    int lane = threadIdx.x & 31;
    const float* basep = logitT + (size_t)gw * SLP;
    float vals[IT];
    float mx = -1e30f;
    #pragma unroll
    for (int i = 0; i < IT; i++) {
        int s = i * 32 + lane;
        float v = (s < NS) ? basep[s] : -1e30f;
        vals[i] = v;
        mx = fmaxf(mx, v);
    }
    #pragma unroll
    for (int o = 16; o; o >>= 1) mx = fmaxf(mx, __shfl_xor_sync(0xffffffffu, mx, o));
    float sum = 0.f;
    #pragma unroll
    for (int i = 0; i < IT; i++) {
        int s = i * 32 + lane;
        float e = (s < NS) ? __expf(vals[i] - mx) : 0.f;
        vals[i] = e;
        sum += e;
    }
    #pragma unroll
    for (int o = 16; o; o >>= 1) sum += __shfl_xor_sync(0xffffffffu, sum, o);
    float inv = 1.f / sum;
    float* dst = probT + (size_t)gw * SLP;
    #pragma unroll
    for (int i = 0; i < IT; i++) {
        int s = i * 32 + lane;
        if (s < NS) dst[s] = vals[i] * inv;
    }
}

// -------- memory passes over mem0 (read-only) --------
__global__ __launch_bounds__(256) void k_slotsum(const float* __restrict__ mem,
                                                 float* __restrict__ part) {
    int b = blockIdx.x, c = blockIdx.y, t = threadIdx.x;
    const float4* m4 = (const float4*)mem + (size_t)(b*Mn + c*MCH)*U4 + t;
    float ax=0.f, ay=0.f, az=0.f, aw=0.f;
    #pragma unroll 8
    for (int i = 0; i < MCH; i++) {
        float4 v = m4[(size_t)i*U4];
        ax += v.x; ay += v.y; az += v.z; aw += v.w;
    }
    ((float4*)part)[(b*NCH + c)*U4 + t] = make_float4(ax, ay, az, aw);
}

// weighted pass: weights = rw (l==0) or rw*A (l>0)
__global__ __launch_bounds__(256) void k_wpass(const float* __restrict__ mem,
                                               const float* __restrict__ rwT,
                                               const float* __restrict__ A,
                                               float* __restrict__ part, int l) {
    __shared__ float ws[MCH][17];
    int b = blockIdx.x, c = blockIdx.y, t = threadIdx.x;
    #pragma unroll
    for (int it = 0; it < 4; it++) {
        int idx = t + 256 * it;
        int hh = idx >> 6, s = idx & 63;
        int m = c * MCH + s;
        float v = rwT[(size_t)(b*Hn + hh)*SLP + m];
        if (l > 0) v *= A[(size_t)(b*Hn + hh)*BHR + m];
        ws[s][hh] = v;
    }
    __syncthreads();
    int h = t >> 4;
    const float4* m4 = (const float4*)mem + (size_t)(b*Mn + c*MCH)*U4 + t;
    float ax=0.f, ay=0.f, az=0.f, aw=0.f;
    #pragma unroll 8
    for (int i = 0; i < MCH; i++) {
        float4 v = m4[(size_t)i*U4];
        float wv = ws[i][h];
        ax += wv*v.x; ay += wv*v.y; az += wv*v.z; aw += wv*v.w;
    }
    ((float4*)part)[(b*NCH + c)*U4 + t] = make_float4(ax, ay, az, aw);
}

// T pass: weights = wA = A_{l-1}*ww_l
__global__ __launch_bounds__(256) void k_tpass(const float* __restrict__ mem,
                                               const float* __restrict__ wA,
                                               float* __restrict__ part) {
    __shared__ float ws[MCH][17];
    int b = blockIdx.x, c = blockIdx.y, t = threadIdx.x;
    #pragma unroll
    for (int it = 0; it < 4; it++) {
        int idx = t + 256 * it;
        int hh = idx >> 6, s = idx & 63;
        ws[s][hh] = wA[(size_t)(b*Hn + hh)*BHR + c*MCH + s];
    }
    __syncthreads();
    int h = t >> 4;
    const float4* m4 = (const float4*)mem + (size_t)(b*Mn + c*MCH)*U4 + t;
    float ax=0.f, ay=0.f, az=0.f, aw=0.f;
    #pragma unroll 8
    for (int i = 0; i < MCH; i++) {
        float4 v = m4[(size_t)i*U4];
        float wv = ws[i][h];
        ax += wv*v.x; ay += wv*v.y; az += wv*v.z; aw += wv*v.w;
    }
    ((float4*)part)[(b*NCH + c)*U4 + t] = make_float4(ax, ay, az, aw);
}

// S update + memstate:  l==0: S=Σpart ; l>0: S-=Σpart.  state=(S + Σ_j sB_j*nv_j + prev)/513
__global__ __launch_bounds__(256) void k_state(const float* __restrict__ part,
                                               float* __restrict__ S,
                                               const float* __restrict__ nv,
                                               const float* __restrict__ sB,
                                               const float* __restrict__ prev,
                                               float* __restrict__ state, int l) {
    int b = blockIdx.x, t = threadIdx.x, h = t >> 4;
    float4 p = make_float4(0.f, 0.f, 0.f, 0.f);
    #pragma unroll
    for (int c = 0; c < NCH; c++) {
        float4 v = ((const float4*)part)[(b*NCH + c)*U4 + t];
        p.x += v.x; p.y += v.y; p.z += v.z; p.w += v.w;
    }
    float4 s;
    if (l == 0) s = p;
    else {
        s = ((const float4*)S)[b*U4 + t];
        s.x -= p.x; s.y -= p.y; s.z -= p.z; s.w -= p.w;
    }
    ((float4*)S)[b*U4 + t] = s;
    float4 a = ((const float4*)prev)[b*U4 + t];
    a.x += s.x; a.y += s.y; a.z += s.z; a.w += s.w;
    for (int j = 0; j < l; j++) {
        float cf = sB[j*Bn*Hn + b*Hn + h];
        float4 n = ((const float4*)nv)[j*NV4 + b*U4 + t];
        a.x += cf*n.x; a.y += cf*n.y; a.z += cf*n.z; a.w += cf*n.w;
    }
    const float inv = 1.f / 513.f;
    a.x *= inv; a.y *= inv; a.z *= inv; a.w *= inv;
    ((float4*)state)[b*U4 + t] = a;
}

// read finalize: read = Σpart + Σ_j (Σ_m rw*B_j)*nv_j + rw[512]*prev
__global__ __launch_bounds__(256) void k_readfin(const float* __restrict__ part,
                                                 const float* __restrict__ rwT,
                                                 const float* __restrict__ B,
                                                 const float* __restrict__ nv,
                                                 const float* __restrict__ prev,
                                                 float* __restrict__ readv, int l) {
    __shared__ float sRB[3][16];
    int b = blockIdx.x, t = threadIdx.x;
    int w = t >> 5, lane = t & 31;
    for (int task = w; task < l * 16; task += 8) {
        int j = task >> 4, h = task & 15;
        const float* rwp = rwT + (size_t)(b*Hn + h)*SLP;
        const float* bp  = B + (size_t)j*BSTR + (size_t)(b*Hn + h)*BHR;
        float s = 0.f;
        #pragma unroll
        for (int i = 0; i < 16; i++) s += rwp[lane + 32*i] * bp[lane + 32*i];
        #pragma unroll
        for (int o = 16; o; o >>= 1) s += __shfl_xor_sync(0xffffffffu, s, o);
        if (lane == 0) sRB[j][h] = s;
    }
    __syncthreads();
    int h = t >> 4;
    float4 a = make_float4(0.f, 0.f, 0.f, 0.f);
    #pragma unroll
    for (int c = 0; c < NCH; c++) {
        float4 v = ((const float4*)part)[(b*NCH + c)*U4 + t];
        a.x += v.x; a.y += v.y; a.z += v.z; a.w += v.w;
    }
    for (int j = 0; j < l; j++) {
        float cf = sRB[j][h];
        float4 n = ((const float4*)nv)[j*NV4 + b*U4 + t];
        a.x += cf*n.x; a.y += cf*n.y; a.z += cf*n.z; a.w += cf*n.w;
    }
    float wl = rwT[(size_t)(b*Hn + h)*SLP + Mn];
    float4 pv = ((const float4*)prev)[b*U4 + t];
    a.x += wl*pv.x; a.y += wl*pv.y; a.z += wl*pv.z; a.w += wl*pv.w;
    ((float4*)readv)[b*U4 + t] = a;
}

// combine K-split partials + bias + relu -> nv (and optionally outp)
__global__ __launch_bounds__(256) void k_wk_reduce(const float* __restrict__ part,
                                                   const float* __restrict__ bk,
                                                   float* __restrict__ nvout,
                                                   float* __restrict__ out2) {
    int b = blockIdx.x, t = threadIdx.x;
    float4 a = ((const float4*)bk)[t];
    #pragma unroll
    for (int z = 0; z < 4; z++) {
        float4 v = ((const float4*)part)[((size_t)z*Bn + b)*U4 + t];
        a.x += v.x; a.y += v.y; a.z += v.z; a.w += v.w;
    }
    a.x = fmaxf(a.x, 0.f); a.y = fmaxf(a.y, 0.f);
    a.z = fmaxf(a.z, 0.f); a.w = fmaxf(a.w, 0.f);
    ((float4*)nvout)[b*U4 + t] = a;
    if (out2) ((float4*)out2)[b*U4 + t] = a;
}

// coefficient recurrences: wA = A*ww ; A *= (1-ww) ; B_j *= (1-ww) (j<l) ; B_l = ww ;
// sB_j = Σ_m B_j (post-update), j<=l
__global__ __launch_bounds__(128) void k_coef(const float* __restrict__ wwT,
                                              float* __restrict__ A,
                                              float* __restrict__ wA,
                                              float* __restrict__ B,
                                              float* __restrict__ sB, int l) {
    __shared__ float wred[4][4];
    int row = blockIdx.x;           // b*16+h
    int t = threadIdx.x;
    int w = t >> 5, lane = t & 31;
    float4 ww = ((const float4*)(wwT + (size_t)row*SLP))[t];
    float4 om = make_float4(1.f-ww.x, 1.f-ww.y, 1.f-ww.z, 1.f-ww.w);
    float4 aold;
    if (l == 0) aold = make_float4(1.f, 1.f, 1.f, 1.f);
    else        aold = ((const float4*)(A + (size_t)row*BHR))[t];
    if (l < 3) {
        float4 wa = make_float4(aold.x*ww.x, aold.y*ww.y, aold.z*ww.z, aold.w*ww.w);
        ((float4*)(wA + (size_t)row*BHR))[t] = wa;
    }
    ((float4*)(A + (size_t)row*BHR))[t] =
        make_float4(aold.x*om.x, aold.y*om.y, aold.z*om.z, aold.w*om.w);
    float sums[4] = {0.f, 0.f, 0.f, 0.f};
    for (int j = 0; j < l; j++) {
        float4* bp = (float4*)(B + (size_t)j*BSTR + (size_t)row*BHR);
        float4 bv = bp[t];
        bv.x *= om.x; bv.y *= om.y; bv.z *= om.z; bv.w *= om.w;
        bp[t] = bv;
        sums[j] = bv.x + bv.y + bv.z + bv.w;
    }
    ((float4*)(B + (size_t)l*BSTR + (size_t)row*BHR))[t] = ww;
    sums[l] = ww.x + ww.y + ww.z + ww.w;
    for (int j = 0; j <= l; j++) {
        float s = sums[j];
        #pragma unroll
        for (int o = 16; o; o >>= 1) s += __shfl_xor_sync(0xffffffffu, s, o);
        if (lane == 0) wred[w][j] = s;
    }
    __syncthreads();
    if (t == 0) {
        for (int j = 0; j <= l; j++)
            sB[j*Bn*Hn + row] = wred[0][j] + wred[1][j] + wred[2][j] + wred[3][j];
    }
}

// final reconstruction: out = A*mem0 + Σ_j B_j*nv_j
__global__ __launch_bounds__(256) void k_recon(const float* __restrict__ mem,
                                               const float* __restrict__ A,
                                               const float* __restrict__ B,
                                               const float* __restrict__ nv,
                                               float* __restrict__ outm) {
    __shared__ float sA[MCH][17];
    __shared__ float sBs[4][MCH][17];
    int b = blockIdx.x, c = blockIdx.y, t = threadIdx.x;
    #pragma unroll
    for (int it = 0; it < 4; it++) {
        int idx = t + 256 * it;
        int hh = idx >> 6, s = idx & 63;
        size_t ro = (size_t)(b*Hn + hh)*BHR + c*MCH + s;
        sA[s][hh] = A[ro];
        #pragma unroll
        for (int j = 0; j < 4; j++) sBs[j][s][hh] = B[(size_t)j*BSTR + ro];
    }
    __syncthreads();
    int h = t >> 4;
    float4 n0 = ((const float4*)nv)[0*NV4 + b*U4 + t];
    float4 n1 = ((const float4*)nv)[1*NV4 + b*U4 + t];
    float4 n2 = ((const float4*)nv)[2*NV4 + b*U4 + t];
    float4 n3 = ((const float4*)nv)[3*NV4 + b*U4 + t];
    size_t basei = (size_t)(b*Mn + c*MCH)*U4 + t;
    const float4* mi = (const float4*)mem;
    float4* mo = (float4*)outm;
    #pragma unroll 4
    for (int i = 0; i < MCH; i++) {
        float4 v = mi[basei + (size_t)i*U4];
        float a  = sA[i][h];
        float b0 = sBs[0][i][h], b1 = sBs[1][i][h], b2 = sBs[2][i][h], b3 = sBs[3][i][h];
        float4 r;
        r.x = a*v.x + b0*n0.x + b1*n1.x + b2*n2.x + b3*n3.x;
        r.y = a*v.y + b0*n0.y + b1*n1.y + b2*n2.y + b3*n3.y;
        r.z = a*v.z + b0*n0.z + b1*n1.z + b2*n2.z + b3*n3.z;
        r.w = a*v.w + b0*n0.w + b1*n1.w + b2*n2.w + b3*n3.w;
        mo[basei + (size_t)i*U4] = r;
    }
}

// -------- host orchestration --------
extern "C" void kernel_launch(void* const* d_in, const int* in_sizes, int n_in,
                              void* d_out, int out_size) {
    const float* x      = (const float*)d_in[0];
    const float* mem0   = (const float*)d_in[1];
    const float* Wr     = (const float*)d_in[2];
    const float* br     = (const float*)d_in[3];
    const float* Ww     = (const float*)d_in[4];
    const float* bw     = (const float*)d_in[5];
    const float* Wk     = (const float*)d_in[6];
    const float* bk     = (const float*)d_in[7];
    float* outp    = (float*)d_out;
    float* out_mem = outp + Bn*Un;

    float *p_part, *p_S, *p_state, *p_rlogT, *p_rwT, *p_wlogT, *p_wwT;
    float *p_read, *p_nv, *p_kpart, *p_A, *p_wA, *p_B, *p_sB;
    cudaGetSymbolAddress((void**)&p_part,  g_part);
    cudaGetSymbolAddress((void**)&p_S,     g_S);
    cudaGetSymbolAddress((void**)&p_state, g_state);
    cudaGetSymbolAddress((void**)&p_rlogT, g_rlogT);
    cudaGetSymbolAddress((void**)&p_rwT,   g_rwT);
    cudaGetSymbolAddress((void**)&p_wlogT, g_wlogT);
    cudaGetSymbolAddress((void**)&p_wwT,   g_wwT);
    cudaGetSymbolAddress((void**)&p_read,  g_read);
    cudaGetSymbolAddress((void**)&p_nv,    g_nv);
    cudaGetSymbolAddress((void**)&p_kpart, g_kpart);
    cudaGetSymbolAddress((void**)&p_A,     g_A);
    cudaGetSymbolAddress((void**)&p_wA,    g_wA);
    cudaGetSymbolAddress((void**)&p_B,     g_B);
    cudaGetSymbolAddress((void**)&p_sB,    g_sB);

    dim3 blk(256);
    k_slotsum<<<dim3(Bn, NCH), blk>>>(mem0, p_part);

    const float* prev = x;
    for (int l = 0; l < Dn; l++) {
        float* nv_l = p_nv + (size_t)l * Bn * Un;

        k_state<<<Bn, blk>>>(p_part, p_S, p_nv, p_sB, prev, p_state, l);
        k_gemm_bf16T<<<129, blk>>>(p_state, Wr + (size_t)l*Un*NRr, br + (size_t)l*NRr,
                                   p_rlogT, NRr);
        k_softmaxT<NSLOT><<<128, blk>>>(p_rlogT, p_rwT);

        k_wpass<<<dim3(Bn, NCH), blk>>>(mem0, p_rwT, p_A, p_part, l);
        k_readfin<<<Bn, blk>>>(p_part, p_rwT, p_B, p_nv, prev, p_read, l);

        k_gemm_x3<<<dim3(16, 1, 4), blk>>>(p_read, Wk + (size_t)l*Un*Un, p_kpart);
        k_wk_reduce<<<Bn, blk>>>(p_kpart, bk + (size_t)l*Un, nv_l,
                                 (l == Dn-1) ? outp : (float*)nullptr);

        k_gemm_bf16T<<<128, blk>>>(nv_l, Ww + (size_t)l*Un*NWw, bw + (size_t)l*NWw,
                                   p_wlogT, NWw);
        k_softmaxT<Mn><<<128, blk>>>(p_wlogT, p_wwT);

        k_coef<<<Bn*Hn, 128>>>(p_wwT, p_A, p_wA, p_B, p_sB, l);
        if (l < Dn - 1)
            k_tpass<<<dim3(Bn, NCH), blk>>>(mem0, p_wA, p_part);

        prev = nv_l;
    }

    k_recon<<<dim3(Bn, NCH), blk>>>(mem0, p_A, p_B, p_nv, out_mem);
}

// round 5
// speedup vs baseline: 2.0727x; 1.1258x over previous
#include <cuda_runtime.h>
#include <cuda_bf16.h>
#include <math.h>
#include <stdint.h>

// Problem constants
#define Bn 64
#define Un 1024
#define Hn 16
#define Mn 512
#define Dn 4
#define NSLOT 513
#define NRr 8208
#define NWw 8192
#define U4 256
#define MCH 64
#define NCH 8
#define SLP 520
#define BHR 512
#define BSTR 524288
#define NV4 16384

// -------- scratch --------
__device__ __nv_bfloat16 g_memh[Bn*Mn*Un];   // bf16 copy of mem0
__device__ float g_part [Bn*NCH*Un];
__device__ float g_S    [Bn*Un];             // running Σ A·mem (state path)
__device__ float g_slot [Bn*Un];             // fp32 Σ_m mem0 (fixed)
__device__ float g_state[Bn*Un];
__device__ float g_rlogT[Bn*Hn*SLP];
__device__ float g_rwT  [Bn*Hn*SLP];
__device__ float g_wlogT[Bn*Hn*SLP];
__device__ float g_cmean[Bn*Hn];             // per-(b,h) mean of wpass weights
__device__ float g_read [Bn*Un];
__device__ float g_nv   [4*Bn*Un];
__device__ float g_kpart[4*Bn*Un];
__device__ float g_A    [Bn*Hn*BHR];
__device__ float g_wA   [Bn*Hn*BHR];
__device__ float g_B    [4*Bn*Hn*BHR];
__device__ float g_sB   [4*Bn*Hn];

// -------- helpers --------
static __device__ __forceinline__ uint32_t smem_u32(const void* p) {
    return (uint32_t)__cvta_generic_to_shared(p);
}
static __device__ __forceinline__ uint32_t pk2(float a, float b) {
    __nv_bfloat162 t = __floats2bfloat162_rn(a, b);
    return *reinterpret_cast<uint32_t*>(&t);
}
static __device__ __forceinline__ float4 bfu2_to_f4(uint2 u) {
    __nv_bfloat162 a = *reinterpret_cast<__nv_bfloat162*>(&u.x);
    __nv_bfloat162 b = *reinterpret_cast<__nv_bfloat162*>(&u.y);
    float2 fa = __bfloat1622float2(a), fb = __bfloat1622float2(b);
    return make_float4(fa.x, fa.y, fb.x, fb.y);
}
static __device__ __forceinline__ void split_pk(float x, float y, uint32_t& hi, uint32_t& lo) {
    __nv_bfloat16 hx = __float2bfloat16(x);
    __nv_bfloat16 hy = __float2bfloat16(y);
    __nv_bfloat162 h2; h2.x = hx; h2.y = hy;
    hi = *reinterpret_cast<uint32_t*>(&h2);
    __nv_bfloat162 l2 = __floats2bfloat162_rn(x - __bfloat162float(hx),
                                              y - __bfloat162float(hy));
    lo = *reinterpret_cast<uint32_t*>(&l2);
}
static __device__ __forceinline__ void ldsm4(uint32_t r[4], uint32_t addr) {
    asm volatile("ldmatrix.sync.aligned.m8n8.x4.shared.b16 {%0,%1,%2,%3}, [%4];"
                 : "=r"(r[0]), "=r"(r[1]), "=r"(r[2]), "=r"(r[3]) : "r"(addr));
}
static __device__ __forceinline__ void ldsm4t(uint32_t r[4], uint32_t addr) {
    asm volatile("ldmatrix.sync.aligned.m8n8.x4.trans.shared.b16 {%0,%1,%2,%3}, [%4];"
                 : "=r"(r[0]), "=r"(r[1]), "=r"(r[2]), "=r"(r[3]) : "r"(addr));
}
static __device__ __forceinline__ void mma16816(float c[4], const uint32_t a[4],
                                                uint32_t b0, uint32_t b1) {
    asm volatile("mma.sync.aligned.m16n8k16.row.col.f32.bf16.bf16.f32 "
                 "{%0,%1,%2,%3}, {%4,%5,%6,%7}, {%8,%9}, {%0,%1,%2,%3};"
                 : "+f"(c[0]), "+f"(c[1]), "+f"(c[2]), "+f"(c[3])
                 : "r"(a[0]), "r"(a[1]), "r"(a[2]), "r"(a[3]), "r"(b0), "r"(b1));
}

// -------- bf16 TC GEMM, transposed epilogue + fused bias --------
__global__ __launch_bounds__(256) void k_gemm_bf16T(const float* __restrict__ A,
                                                    const float* __restrict__ W,
                                                    const float* __restrict__ bias,
                                                    float* __restrict__ dstT,
                                                    int N) {
    __shared__ uint4 Asm[2][512];
    __shared__ uint4 Bsm[2][512];
    const int t = threadIdx.x;
    const int n0 = blockIdx.x * 64;
    const int lane = t & 31, w = t >> 5;
    const int m0 = (w & 3) * 16;
    const int nw0 = (w >> 2) * 32;
    const uint32_t aBase = smem_u32(Asm);
    const uint32_t bBase = smem_u32(Bsm);

    float acc[4][4];
    #pragma unroll
    for (int j = 0; j < 4; j++)
        #pragma unroll
        for (int r = 0; r < 4; r++) acc[j][r] = 0.f;

    float4 ra[2][2], rb[2][2];
    auto loadStage = [&](int k0) {
        #pragma unroll
        for (int it = 0; it < 2; it++) {
            int idx = t + 256 * it;
            int r = idx >> 3, c = idx & 7;
            const float* ap = A + r * Un + k0 + c * 8;
            ra[it][0] = *(const float4*)ap;
            ra[it][1] = *(const float4*)(ap + 4);
            int n = n0 + c * 8;
            const float* wp = W + (size_t)(k0 + r) * N + n;
            if (n + 7 < N) {
                rb[it][0] = *(const float4*)wp;
                rb[it][1] = *(const float4*)(wp + 4);
            } else {
                float v[8];
                #pragma unroll
                for (int j = 0; j < 8; j++) v[j] = (n + j < N) ? wp[j] : 0.f;
                rb[it][0] = make_float4(v[0], v[1], v[2], v[3]);
                rb[it][1] = make_float4(v[4], v[5], v[6], v[7]);
            }
        }
    };
    auto stsStage = [&](int buf) {
        #pragma unroll
        for (int it = 0; it < 2; it++) {
            int idx = t + 256 * it;
            int r = idx >> 3, c = idx & 7;
            int u = r * 8 + (c ^ (r & 7));
            Asm[buf][u] = make_uint4(pk2(ra[it][0].x, ra[it][0].y), pk2(ra[it][0].z, ra[it][0].w),
                                     pk2(ra[it][1].x, ra[it][1].y), pk2(ra[it][1].z, ra[it][1].w));
            Bsm[buf][u] = make_uint4(pk2(rb[it][0].x, rb[it][0].y), pk2(rb[it][0].z, rb[it][0].w),
                                     pk2(rb[it][1].x, rb[it][1].y), pk2(rb[it][1].z, rb[it][1].w));
        }
    };

    loadStage(0);
    stsStage(0);
    __syncthreads();

    for (int ch = 0; ch < 16; ch++) {
        if (ch < 15) loadStage((ch + 1) * 64);
        const int buf = ch & 1;
        const uint32_t aB = aBase + buf * 8192;
        const uint32_t bB = bBase + buf * 8192;
        #pragma unroll
        for (int ksi = 0; ksi < 4; ksi++) {
            const int ks = ksi * 16;
            uint32_t af[4], bf0[4], bf1[4];
            { int r = m0 + (lane & 15), c = (ks >> 3) + (lane >> 4);
              ldsm4(af, aB + (uint32_t)(r * 8 + (c ^ (r & 7))) * 16); }
            { int r = ks + (lane & 15), c = (nw0 >> 3) + (lane >> 4);
              ldsm4t(bf0, bB + (uint32_t)(r * 8 + (c ^ (r & 7))) * 16); }
            { int r = ks + (lane & 15), c = ((nw0 + 16) >> 3) + (lane >> 4);
              ldsm4t(bf1, bB + (uint32_t)(r * 8 + (c ^ (r & 7))) * 16); }
            mma16816(acc[0], af, bf0[0], bf0[1]);
            mma16816(acc[1], af, bf0[2], bf0[3]);
            mma16816(acc[2], af, bf1[0], bf1[1]);
            mma16816(acc[3], af, bf1[2], bf1[3]);
        }
        if (ch < 15) stsStage(buf ^ 1);
        __syncthreads();
    }

    const int g = lane >> 2, tg = lane & 3;
    #pragma unroll
    for (int j = 0; j < 4; j++) {
        int ncol = n0 + nw0 + j * 8 + tg * 2;
        int m_lo = m0 + g, m_hi = m0 + g + 8;
        #pragma unroll
        for (int e = 0; e < 2; e++) {
            int n = ncol + e;
            if (n < N) {
                float bv = bias[n];
                int h = n & 15, s = n >> 4;
                dstT[(size_t)(m_lo * Hn + h) * SLP + s] = acc[j][e] + bv;
                dstT[(size_t)(m_hi * Hn + h) * SLP + s] = acc[j][2 + e] + bv;
            }
        }
    }
}

// -------- bf16x3 split GEMM for Wk --------
__global__ __launch_bounds__(256) void k_gemm_x3(const float* __restrict__ A,
                                                 const float* __restrict__ W,
                                                 float* __restrict__ kpart) {
    __shared__ uint4 S4[4][512];
    const int t = threadIdx.x;
    const int n0 = blockIdx.x * 64;
    const int kb = blockIdx.z * 256;
    const int lane = t & 31, w = t >> 5;
    const int m0 = (w & 3) * 16;
    const int nw0 = (w >> 2) * 32;
    const uint32_t base = smem_u32(S4);

    float acc[4][4];
    #pragma unroll
    for (int j = 0; j < 4; j++)
        #pragma unroll
        for (int r = 0; r < 4; r++) acc[j][r] = 0.f;

    for (int ch = 0; ch < 4; ch++) {
        int k0 = kb + ch * 64;
        float4 ra[2][2], rb[2][2];
        #pragma unroll
        for (int it = 0; it < 2; it++) {
            int idx = t + 256 * it;
            int r = idx >> 3, c = idx & 7;
            const float* ap = A + r * Un + k0 + c * 8;
            ra[it][0] = *(const float4*)ap;
            ra[it][1] = *(const float4*)(ap + 4);
            const float* wp = W + (size_t)(k0 + r) * Un + n0 + c * 8;
            rb[it][0] = *(const float4*)wp;
            rb[it][1] = *(const float4*)(wp + 4);
        }
        __syncthreads();
        #pragma unroll
        for (int it = 0; it < 2; it++) {
            int idx = t + 256 * it;
            int r = idx >> 3, c = idx & 7;
            int u = r * 8 + (c ^ (r & 7));
            uint32_t h0,l0,h1,l1,h2,l2,h3,l3;
            split_pk(ra[it][0].x, ra[it][0].y, h0, l0);
            split_pk(ra[it][0].z, ra[it][0].w, h1, l1);
            split_pk(ra[it][1].x, ra[it][1].y, h2, l2);
            split_pk(ra[it][1].z, ra[it][1].w, h3, l3);
            S4[0][u] = make_uint4(h0, h1, h2, h3);
            S4[1][u] = make_uint4(l0, l1, l2, l3);
            split_pk(rb[it][0].x, rb[it][0].y, h0, l0);
            split_pk(rb[it][0].z, rb[it][0].w, h1, l1);
            split_pk(rb[it][1].x, rb[it][1].y, h2, l2);
            split_pk(rb[it][1].z, rb[it][1].w, h3, l3);
            S4[2][u] = make_uint4(h0, h1, h2, h3);
            S4[3][u] = make_uint4(l0, l1, l2, l3);
        }
        __syncthreads();
        #pragma unroll
        for (int ksi = 0; ksi < 4; ksi++) {
            const int ks = ksi * 16;
            uint32_t ah[4], al[4], bh0[4], bh1[4], bl0[4], bl1[4];
            int ra_ = m0 + (lane & 15), ca = (ks >> 3) + (lane >> 4);
            uint32_t aoff = (uint32_t)(ra_ * 8 + (ca ^ (ra_ & 7))) * 16;
            ldsm4(ah, base + aoff);
            ldsm4(al, base + 8192 + aoff);
            int rb_ = ks + (lane & 15);
            int cb0 = (nw0 >> 3) + (lane >> 4), cb1 = ((nw0 + 16) >> 3) + (lane >> 4);
            uint32_t b0off = (uint32_t)(rb_ * 8 + (cb0 ^ (rb_ & 7))) * 16;
            uint32_t b1off = (uint32_t)(rb_ * 8 + (cb1 ^ (rb_ & 7))) * 16;
            ldsm4t(bh0, base + 16384 + b0off);
            ldsm4t(bh1, base + 16384 + b1off);
            ldsm4t(bl0, base + 24576 + b0off);
            ldsm4t(bl1, base + 24576 + b1off);
            mma16816(acc[0], ah, bh0[0], bh0[1]);
            mma16816(acc[0], ah, bl0[0], bl0[1]);
            mma16816(acc[0], al, bh0[0], bh0[1]);
            mma16816(acc[1], ah, bh0[2], bh0[3]);
            mma16816(acc[1], ah, bl0[2], bl0[3]);
            mma16816(acc[1], al, bh0[2], bh0[3]);
            mma16816(acc[2], ah, bh1[0], bh1[1]);
            mma16816(acc[2], ah, bl1[0], bl1[1]);
            mma16816(acc[2], al, bh1[0], bh1[1]);
            mma16816(acc[3], ah, bh1[2], bh1[3]);
            mma16816(acc[3], ah, bl1[2], bl1[3]);
            mma16816(acc[3], al, bh1[2], bh1[3]);
        }
    }
    size_t zo = (size_t)blockIdx.z * Bn * Un;
    const int g = lane >> 2, tg = lane & 3;
    #pragma unroll
    for (int j = 0; j < 4; j++) {
        int ncol = n0 + nw0 + j * 8 + tg * 2;
        int m_lo = m0 + g, m_hi = m0 + g + 8;
        *(float2*)&kpart[zo + (size_t)m_lo * Un + ncol] = make_float2(acc[j][0], acc[j][1]);
        *(float2*)&kpart[zo + (size_t)m_hi * Un + ncol] = make_float2(acc[j][2], acc[j][3]);
    }
}

// -------- rw softmax (513 slots) + wpass-weight mean c = (Σ_{m<512} rw·A)/512 --------
__global__ __launch_bounds__(256) void k_softmax513(const float* __restrict__ logitT,
                                                    float* __restrict__ probT,
                                                    const float* __restrict__ A,
                                                    float* __restrict__ cArr, int l) {
    constexpr int IT = 17;
    int gw = (blockIdx.x * 256 + threadIdx.x) >> 5;
    int lane = threadIdx.x & 31;
    const float* basep = logitT + (size_t)gw * SLP;
    float vals[IT];
    float mx = -1e30f;
    #pragma unroll
    for (int i = 0; i < IT; i++) {
        int s = i * 32 + lane;
        float v = (s < NSLOT) ? basep[s] : -1e30f;
        vals[i] = v;
        mx = fmaxf(mx, v);
    }
    #pragma unroll
    for (int o = 16; o; o >>= 1) mx = fmaxf(mx, __shfl_xor_sync(0xffffffffu, mx, o));
    float sum = 0.f;
    #pragma unroll
    for (int i = 0; i < IT; i++) {
        int s = i * 32 + lane;
        float e = (s < NSLOT) ? __expf(vals[i] - mx) : 0.f;
        vals[i] = e;
        sum += e;
    }
    #pragma unroll
    for (int o = 16; o; o >>= 1) sum += __shfl_xor_sync(0xffffffffu, sum, o);
    float inv = 1.f / sum;
    float* dst = probT + (size_t)gw * SLP;
    #pragma unroll
    for (int i = 0; i < IT; i++) {
        int s = i * 32 + lane;
        if (s < NSLOT) dst[s] = vals[i] * inv;
    }
    // mean of the memory-slot weights (rw or rw*A), excluding input slot
    float dot = 0.f;
    if (l > 0) {
        const float* ap = A + (size_t)gw * BHR;
        #pragma unroll
        for (int i = 0; i < 16; i++) dot += vals[i] * inv * ap[i * 32 + lane];
    } else {
        #pragma unroll
        for (int i = 0; i < 16; i++) dot += vals[i] * inv;
    }
    #pragma unroll
    for (int o = 16; o; o >>= 1) dot += __shfl_xor_sync(0xffffffffu, dot, o);
    if (lane == 0) cArr[gw] = dot * (1.f / 512.f);
}

// -------- fused ww-softmax + coefficient recurrence --------
__global__ __launch_bounds__(128) void k_smcoef(const float* __restrict__ wlogT,
                                                float* __restrict__ A,
                                                float* __restrict__ wA,
                                                float* __restrict__ B,
                                                float* __restrict__ sB, int l) {
    __shared__ float redm[4], reds[4], wred[4][4];
    int row = blockIdx.x;
    int t = threadIdx.x;
    int w = t >> 5, lane = t & 31;

    float4 lg = ((const float4*)(wlogT + (size_t)row*SLP))[t];
    float mx = fmaxf(fmaxf(lg.x, lg.y), fmaxf(lg.z, lg.w));
    #pragma unroll
    for (int o = 16; o; o >>= 1) mx = fmaxf(mx, __shfl_xor_sync(0xffffffffu, mx, o));
    if (lane == 0) redm[w] = mx;
    __syncthreads();
    mx = fmaxf(fmaxf(redm[0], redm[1]), fmaxf(redm[2], redm[3]));
    float4 e = make_float4(__expf(lg.x - mx), __expf(lg.y - mx),
                           __expf(lg.z - mx), __expf(lg.w - mx));
    float s = e.x + e.y + e.z + e.w;
    #pragma unroll
    for (int o = 16; o; o >>= 1) s += __shfl_xor_sync(0xffffffffu, s, o);
    if (lane == 0) reds[w] = s;
    __syncthreads();
    float inv = 1.f / (reds[0] + reds[1] + reds[2] + reds[3]);
    float4 ww = make_float4(e.x * inv, e.y * inv, e.z * inv, e.w * inv);

    float4 om = make_float4(1.f-ww.x, 1.f-ww.y, 1.f-ww.z, 1.f-ww.w);
    float4 aold;
    if (l == 0) aold = make_float4(1.f, 1.f, 1.f, 1.f);
    else        aold = ((const float4*)(A + (size_t)row*BHR))[t];
    if (l < 3) {
        ((float4*)(wA + (size_t)row*BHR))[t] =
            make_float4(aold.x*ww.x, aold.y*ww.y, aold.z*ww.z, aold.w*ww.w);
    }
    ((float4*)(A + (size_t)row*BHR))[t] =
        make_float4(aold.x*om.x, aold.y*om.y, aold.z*om.z, aold.w*om.w);
    float sums[4] = {0.f, 0.f, 0.f, 0.f};
    for (int j = 0; j < l; j++) {
        float4* bp = (float4*)(B + (size_t)j*BSTR + (size_t)row*BHR);
        float4 bv = bp[t];
        bv.x *= om.x; bv.y *= om.y; bv.z *= om.z; bv.w *= om.w;
        bp[t] = bv;
        sums[j] = bv.x + bv.y + bv.z + bv.w;
    }
    ((float4*)(B + (size_t)l*BSTR + (size_t)row*BHR))[t] = ww;
    sums[l] = ww.x + ww.y + ww.z + ww.w;
    for (int j = 0; j <= l; j++) {
        float ss = sums[j];
        #pragma unroll
        for (int o = 16; o; o >>= 1) ss += __shfl_xor_sync(0xffffffffu, ss, o);
        if (lane == 0) wred[w][j] = ss;
    }
    __syncthreads();
    if (t == 0) {
        for (int j = 0; j <= l; j++)
            sB[j*Bn*Hn + row] = wred[0][j] + wred[1][j] + wred[2][j] + wred[3][j];
    }
}

// -------- initial: fp32 slot-sum partials + bf16 conversion --------
__global__ __launch_bounds__(256) void k_convsum(const float* __restrict__ mem,
                                                 __nv_bfloat16* __restrict__ memh,
                                                 float* __restrict__ part) {
    int b = blockIdx.x, c = blockIdx.y, t = threadIdx.x;
    size_t base = (size_t)(b*Mn + c*MCH)*U4 + t;
    const float4* m4 = (const float4*)mem + base;
    uint2* o2 = (uint2*)memh + base;
    float ax=0.f, ay=0.f, az=0.f, aw=0.f;
    #pragma unroll 8
    for (int i = 0; i < MCH; i++) {
        float4 v = m4[(size_t)i*U4];
        ax += v.x; ay += v.y; az += v.z; aw += v.w;
        __nv_bfloat162 p0 = __floats2bfloat162_rn(v.x, v.y);
        __nv_bfloat162 p1 = __floats2bfloat162_rn(v.z, v.w);
        o2[(size_t)i*U4] = make_uint2(*reinterpret_cast<uint32_t*>(&p0),
                                      *reinterpret_cast<uint32_t*>(&p1));
    }
    ((float4*)part)[(b*NCH + c)*U4 + t] = make_float4(ax, ay, az, aw);
}

// -------- mean-subtracted weighted pass over bf16 mem --------
__global__ __launch_bounds__(256) void k_wpass(const __nv_bfloat16* __restrict__ memh,
                                               const float* __restrict__ rwT,
                                               const float* __restrict__ A,
                                               const float* __restrict__ cArr,
                                               float* __restrict__ part, int l) {
    __shared__ float ws[MCH][17];
    int b = blockIdx.x, c = blockIdx.y, t = threadIdx.x;
    #pragma unroll
    for (int it = 0; it < 4; it++) {
        int idx = t + 256 * it;
        int hh = idx >> 6, s = idx & 63;
        int m = c * MCH + s;
        float v = rwT[(size_t)(b*Hn + hh)*SLP + m];
        if (l > 0) v *= A[(size_t)(b*Hn + hh)*BHR + m];
        ws[s][hh] = v - cArr[b*Hn + hh];
    }
    __syncthreads();
    int h = t >> 4;
    const uint2* m2 = (const uint2*)memh + (size_t)(b*Mn + c*MCH)*U4 + t;
    float ax=0.f, ay=0.f, az=0.f, aw=0.f;
    #pragma unroll 8
    for (int i = 0; i < MCH; i++) {
        float4 v = bfu2_to_f4(m2[(size_t)i*U4]);
        float wv = ws[i][h];
        ax += wv*v.x; ay += wv*v.y; az += wv*v.z; aw += wv*v.w;
    }
    ((float4*)part)[(b*NCH + c)*U4 + t] = make_float4(ax, ay, az, aw);
}

// -------- T pass over bf16 mem (state path; no mean subtraction needed) --------
__global__ __launch_bounds__(256) void k_tpass(const __nv_bfloat16* __restrict__ memh,
                                               const float* __restrict__ wA,
                                               float* __restrict__ part) {
    __shared__ float ws[MCH][17];
    int b = blockIdx.x, c = blockIdx.y, t = threadIdx.x;
    #pragma unroll
    for (int it = 0; it < 4; it++) {
        int idx = t + 256 * it;
        int hh = idx >> 6, s = idx & 63;
        ws[s][hh] = wA[(size_t)(b*Hn + hh)*BHR + c*MCH + s];
    }
    __syncthreads();
    int h = t >> 4;
    const uint2* m2 = (const uint2*)memh + (size_t)(b*Mn + c*MCH)*U4 + t;
    float ax=0.f, ay=0.f, az=0.f, aw=0.f;
    #pragma unroll 8
    for (int i = 0; i < MCH; i++) {
        float4 v = bfu2_to_f4(m2[(size_t)i*U4]);
        float wv = ws[i][h];
        ax += wv*v.x; ay += wv*v.y; az += wv*v.z; aw += wv*v.w;
    }
    ((float4*)part)[(b*NCH + c)*U4 + t] = make_float4(ax, ay, az, aw);
}

// -------- S update + memstate (also captures fp32 SlotSum at l=0) --------
__global__ __launch_bounds__(256) void k_state(const float* __restrict__ part,
                                               float* __restrict__ S,
                                               float* __restrict__ slot,
                                               const float* __restrict__ nv,
                                               const float* __restrict__ sB,
                                               const float* __restrict__ prev,
                                               float* __restrict__ state, int l) {
    int b = blockIdx.x, t = threadIdx.x, h = t >> 4;
    float4 p = make_float4(0.f, 0.f, 0.f, 0.f);
    #pragma unroll
    for (int c = 0; c < NCH; c++) {
        float4 v = ((const float4*)part)[(b*NCH + c)*U4 + t];
        p.x += v.x; p.y += v.y; p.z += v.z; p.w += v.w;
    }
    float4 s;
    if (l == 0) {
        s = p;
        ((float4*)slot)[b*U4 + t] = p;   // fp32 Σ_m mem0 (fixed for whole run)
    } else {
        s = ((const float4*)S)[b*U4 + t];
        s.x -= p.x; s.y -= p.y; s.z -= p.z; s.w -= p.w;
    }
    ((float4*)S)[b*U4 + t] = s;
    float4 a = ((const float4*)prev)[b*U4 + t];
    a.x += s.x; a.y += s.y; a.z += s.z; a.w += s.w;
    for (int j = 0; j < l; j++) {
        float cf = sB[j*Bn*Hn + b*Hn + h];
        float4 n = ((const float4*)nv)[j*NV4 + b*U4 + t];
        a.x += cf*n.x; a.y += cf*n.y; a.z += cf*n.z; a.w += cf*n.w;
    }
    const float inv = 1.f / 513.f;
    a.x *= inv; a.y *= inv; a.z *= inv; a.w *= inv;
    ((float4*)state)[b*U4 + t] = a;
}

// -------- read finalize: read = c·Slot + Σpart + Σ_j sRB_j·nv_j + rw[512]·prev --------
__global__ __launch_bounds__(256) void k_readfin(const float* __restrict__ part,
                                                 const float* __restrict__ rwT,
                                                 const float* __restrict__ B,
                                                 const float* __restrict__ nv,
                                                 const float* __restrict__ prev,
                                                 const float* __restrict__ slot,
                                                 const float* __restrict__ cArr,
                                                 float* __restrict__ readv, int l) {
    __shared__ float sRB[3][16];
    int b = blockIdx.x, t = threadIdx.x;
    int w = t >> 5, lane = t & 31;
    for (int task = w; task < l * 16; task += 8) {
        int j = task >> 4, h = task & 15;
        const float* rwp = rwT + (size_t)(b*Hn + h)*SLP;
        const float* bp  = B + (size_t)j*BSTR + (size_t)(b*Hn + h)*BHR;
        float s = 0.f;
        #pragma unroll
        for (int i = 0; i < 16; i++) s += rwp[lane + 32*i] * bp[lane + 32*i];
        #pragma unroll
        for (int o = 16; o; o >>= 1) s += __shfl_xor_sync(0xffffffffu, s, o);
        if (lane == 0) sRB[j][h] = s;
    }
    __syncthreads();
    int h = t >> 4;
    float cc = cArr[b*Hn + h];
    float4 sl = ((const float4*)slot)[b*U4 + t];
    float4 a = make_float4(cc*sl.x, cc*sl.y, cc*sl.z, cc*sl.w);
    #pragma unroll
    for (int c = 0; c < NCH; c++) {
        float4 v = ((const float4*)part)[(b*NCH + c)*U4 + t];
        a.x += v.x; a.y += v.y; a.z += v.z; a.w += v.w;
    }
    for (int j = 0; j < l; j++) {
        float cf = sRB[j][h];
        float4 n = ((const float4*)nv)[j*NV4 + b*U4 + t];
        a.x += cf*n.x; a.y += cf*n.y; a.z += cf*n.z; a.w += cf*n.w;
    }
    float wl = rwT[(size_t)(b*Hn + h)*SLP + Mn];
    float4 pv = ((const float4*)prev)[b*U4 + t];
    a.x += wl*pv.x; a.y += wl*pv.y; a.z += wl*pv.z; a.w += wl*pv.w;
    ((float4*)readv)[b*U4 + t] = a;
}

// -------- combine K-split + bias + relu --------
__global__ __launch_bounds__(256) void k_wk_reduce(const float* __restrict__ part,
                                                   const float* __restrict__ bk,
                                                   float* __restrict__ nvout,
                                                   float* __restrict__ out2) {
    int b = blockIdx.x, t = threadIdx.x;
    float4 a = ((const float4*)bk)[t];
    #pragma unroll
    for (int z = 0; z < 4; z++) {
        float4 v = ((const float4*)part)[((size_t)z*Bn + b)*U4 + t];
        a.x += v.x; a.y += v.y; a.z += v.z; a.w += v.w;
    }
    a.x = fmaxf(a.x, 0.f); a.y = fmaxf(a.y, 0.f);
    a.z = fmaxf(a.z, 0.f); a.w = fmaxf(a.w, 0.f);
    ((float4*)nvout)[b*U4 + t] = a;
    if (out2) ((float4*)out2)[b*U4 + t] = a;
}

// -------- final reconstruction (fp32 mem0) --------
__global__ __launch_bounds__(256) void k_recon(const float* __restrict__ mem,
                                               const float* __restrict__ A,
                                               const float* __restrict__ B,
                                               const float* __restrict__ nv,
                                               float* __restrict__ outm) {
    __shared__ float sA[MCH][17];
    __shared__ float sBs[4][MCH][17];
    int b = blockIdx.x, c = blockIdx.y, t = threadIdx.x;
    #pragma unroll
    for (int it = 0; it < 4; it++) {
        int idx = t + 256 * it;
        int hh = idx >> 6, s = idx & 63;
        size_t ro = (size_t)(b*Hn + hh)*BHR + c*MCH + s;
        sA[s][hh] = A[ro];
        #pragma unroll
        for (int j = 0; j < 4; j++) sBs[j][s][hh] = B[(size_t)j*BSTR + ro];
    }
    __syncthreads();
    int h = t >> 4;
    float4 n0 = ((const float4*)nv)[0*NV4 + b*U4 + t];
    float4 n1 = ((const float4*)nv)[1*NV4 + b*U4 + t];
    float4 n2 = ((const float4*)nv)[2*NV4 + b*U4 + t];
    float4 n3 = ((const float4*)nv)[3*NV4 + b*U4 + t];
    size_t basei = (size_t)(b*Mn + c*MCH)*U4 + t;
    const float4* mi = (const float4*)mem;
    float4* mo = (float4*)outm;
    #pragma unroll 4
    for (int i = 0; i < MCH; i++) {
        float4 v = mi[basei + (size_t)i*U4];
        float a  = sA[i][h];
        float b0 = sBs[0][i][h], b1 = sBs[1][i][h], b2 = sBs[2][i][h], b3 = sBs[3][i][h];
        float4 r;
        r.x = a*v.x + b0*n0.x + b1*n1.x + b2*n2.x + b3*n3.x;
        r.y = a*v.y + b0*n0.y + b1*n1.y + b2*n2.y + b3*n3.y;
        r.z = a*v.z + b0*n0.z + b1*n1.z + b2*n2.z + b3*n3.z;
        r.w = a*v.w + b0*n0.w + b1*n1.w + b2*n2.w + b3*n3.w;
        mo[basei + (size_t)i*U4] = r;
    }
}

// -------- host orchestration --------
extern "C" void kernel_launch(void* const* d_in, const int* in_sizes, int n_in,
                              void* d_out, int out_size) {
    const float* x      = (const float*)d_in[0];
    const float* mem0   = (const float*)d_in[1];
    const float* Wr     = (const float*)d_in[2];
    const float* br     = (const float*)d_in[3];
    const float* Ww     = (const float*)d_in[4];
    const float* bw     = (const float*)d_in[5];
    const float* Wk     = (const float*)d_in[6];
    const float* bk     = (const float*)d_in[7];
    float* outp    = (float*)d_out;
    float* out_mem = outp + Bn*Un;

    float *p_part, *p_S, *p_slot, *p_state, *p_rlogT, *p_rwT, *p_wlogT, *p_c;
    float *p_read, *p_nv, *p_kpart, *p_A, *p_wA, *p_B, *p_sB;
    __nv_bfloat16* p_memh;
    cudaGetSymbolAddress((void**)&p_memh,  g_memh);
    cudaGetSymbolAddress((void**)&p_part,  g_part);
    cudaGetSymbolAddress((void**)&p_S,     g_S);
    cudaGetSymbolAddress((void**)&p_slot,  g_slot);
    cudaGetSymbolAddress((void**)&p_state, g_state);
    cudaGetSymbolAddress((void**)&p_rlogT, g_rlogT);
    cudaGetSymbolAddress((void**)&p_rwT,   g_rwT);
    cudaGetSymbolAddress((void**)&p_wlogT, g_wlogT);
    cudaGetSymbolAddress((void**)&p_c,     g_cmean);
    cudaGetSymbolAddress((void**)&p_read,  g_read);
    cudaGetSymbolAddress((void**)&p_nv,    g_nv);
    cudaGetSymbolAddress((void**)&p_kpart, g_kpart);
    cudaGetSymbolAddress((void**)&p_A,     g_A);
    cudaGetSymbolAddress((void**)&p_wA,    g_wA);
    cudaGetSymbolAddress((void**)&p_B,     g_B);
    cudaGetSymbolAddress((void**)&p_sB,    g_sB);

    dim3 blk(256);
    k_convsum<<<dim3(Bn, NCH), blk>>>(mem0, p_memh, p_part);

    const float* prev = x;
    for (int l = 0; l < Dn; l++) {
        float* nv_l = p_nv + (size_t)l * Bn * Un;

        k_state<<<Bn, blk>>>(p_part, p_S, p_slot, p_nv, p_sB, prev, p_state, l);
        k_gemm_bf16T<<<129, blk>>>(p_state, Wr + (size_t)l*Un*NRr, br + (size_t)l*NRr,
                                   p_rlogT, NRr);
        k_softmax513<<<128, blk>>>(p_rlogT, p_rwT, p_A, p_c, l);

        k_wpass<<<dim3(Bn, NCH), blk>>>(p_memh, p_rwT, p_A, p_c, p_part, l);
        k_readfin<<<Bn, blk>>>(p_part, p_rwT, p_B, p_nv, prev, p_slot, p_c, p_read, l);

        k_gemm_x3<<<dim3(16, 1, 4), blk>>>(p_read, Wk + (size_t)l*Un*Un, p_kpart);
        k_wk_reduce<<<Bn, blk>>>(p_kpart, bk + (size_t)l*Un, nv_l,
                                 (l == Dn-1) ? outp : (float*)nullptr);

        k_gemm_bf16T<<<128, blk>>>(nv_l, Ww + (size_t)l*Un*NWw, bw + (size_t)l*NWw,
                                   p_wlogT, NWw);
        k_smcoef<<<Bn*Hn, 128>>>(p_wlogT, p_A, p_wA, p_B, p_sB, l);

        if (l < Dn - 1)
            k_tpass<<<dim3(Bn, NCH), blk>>>(p_memh, p_wA, p_part);

        prev = nv_l;
    }

    k_recon<<<dim3(Bn, NCH), blk>>>(mem0, p_A, p_B, p_nv, out_mem);
}